// round 3
// baseline (speedup 1.0000x reference)
#include <cuda_runtime.h>
#include <math.h>

#define NN 50000
#define HH 128
#define NPAD 50048            // 391*128, padded rows for K3 GEMM (zero-init)
#define TN 16                 // nodes per tile (16*8 = 128 rows)
#define NTILES (NN/TN)        // 3125

// ---------------- scratch (__device__ globals; zero-initialized) ----------------
__device__ float g_T[2*128*384];              // Wd@U0 | Wa@U1
__device__ float g_G[384*384];                // [vf@Wd@U0 ; vf@Wa@U1 ; Wiou]
__device__ float g_qv[128];                   // Qf @ Vf
__device__ float g_Z[(size_t)NPAD*384];       // [sB | sA | x]
__device__ float g_IOU[(size_t)NPAD*384];
__device__ float g_cred[(size_t)NN*128];

// ---------------- K1a: T0 = Wd@U0, T1 = Wa@U1 ----------------
__global__ void k1a(const float* __restrict__ Wa, const float* __restrict__ Wd,
                    const float* __restrict__ Uiou) {
    int idx = blockIdx.x * blockDim.x + threadIdx.x;
    if (idx >= 2*128*384) return;
    int which = idx / (128*384);
    int rem   = idx - which*(128*384);
    int m = rem / 384, j = rem - m*384;
    const float* W = which ? Wa : Wd;
    const float* U = Uiou + which*(128*384);
    float s = 0.f;
#pragma unroll 8
    for (int z = 0; z < 128; z++) s += W[m*128+z] * U[z*384+j];
    g_T[idx] = s;
}

// ---------------- K1b: G rows; qv = Qf@Vf ----------------
__global__ void k1b(const float* __restrict__ vf, const float* __restrict__ Wiou,
                    const float* __restrict__ Qf, const float* __restrict__ Vf) {
    int idx = blockIdx.x * blockDim.x + threadIdx.x;
    if (idx < 2*128*384) {
        int which = idx / (128*384);
        int rem   = idx - which*(128*384);
        int m = rem / 384, j = rem - m*384;
        const float* T = g_T + which*(128*384);
        float s = 0.f;
#pragma unroll 8
        for (int z = 0; z < 128; z++) s += vf[m*128+z] * T[z*384+j];
        g_G[idx] = s;
    } else if (idx < 3*128*384) {
        int rem = idx - 2*128*384;
        g_G[idx] = Wiou[rem];
    } else if (idx < 3*128*384 + 128) {
        int m = idx - 3*128*384;
        float s = 0.f;
#pragma unroll 8
        for (int j = 0; j < 128; j++) s += Qf[m*128+j] * Vf[j];
        g_qv[m] = s;
    }
}

// ---------------- K2A: hk = h_mail@Kf, scores, softmax, weighted sums -> Z ----------------
// smem floats: Kf 16384 | As 32*132 | Vf 128 | qv 128
#define K2A_SMEM ((128*128 + 32*132 + 128 + 128) * 4)
__global__ void __launch_bounds__(256, 2)
k2a(const float* __restrict__ x, const float* __restrict__ hmail,
    const float* __restrict__ Kf, const float* __restrict__ Vf,
    const int* __restrict__ etype) {
    extern __shared__ float sm[];
    float* Bs  = sm;                  // Kf, 128x128
    float* As  = Bs + 128*128;        // chunk, 32x132 (transposed, padded)
    float* Vfs = As + 32*132;
    float* qvs = Vfs + 128;
    const int tid = threadIdx.x, tx = tid & 15, ty = tid >> 4;

    for (int i = tid; i < 128*128/4; i += 256)
        ((float4*)Bs)[i] = ((const float4*)Kf)[i];
    if (tid < 128) { Vfs[tid] = Vf[tid]; qvs[tid] = g_qv[tid]; }
    __syncthreads();

    for (int tile = blockIdx.x; tile < NTILES; tile += gridDim.x) {
        float acc[8][8];
#pragma unroll
        for (int a = 0; a < 8; a++)
#pragma unroll
            for (int b = 0; b < 8; b++) acc[a][b] = 0.f;

        const float* At = hmail + (size_t)tile * (128*128);
        for (int kb = 0; kb < 128; kb += 32) {
            __syncthreads();
            {   // load 128x32 chunk transposed
                int cg = tid & 7, r0 = tid >> 3;
#pragma unroll
                for (int p = 0; p < 4; p++) {
                    int r = r0 + p*32;
                    float4 v = *(const float4*)(At + r*128 + kb + cg*4);
                    As[(cg*4+0)*132 + r] = v.x;
                    As[(cg*4+1)*132 + r] = v.y;
                    As[(cg*4+2)*132 + r] = v.z;
                    As[(cg*4+3)*132 + r] = v.w;
                }
            }
            __syncthreads();
#pragma unroll 8
            for (int kk = 0; kk < 32; kk++) {
                float4 a0 = *(const float4*)(As + kk*132 + ty*8);
                float4 a1 = *(const float4*)(As + kk*132 + ty*8 + 4);
                float4 b0 = *(const float4*)(Bs + (kb+kk)*128 + tx*4);
                float4 b1 = *(const float4*)(Bs + (kb+kk)*128 + 64 + tx*4);
                float a[8] = {a0.x,a0.y,a0.z,a0.w,a1.x,a1.y,a1.z,a1.w};
                float b[8] = {b0.x,b0.y,b0.z,b0.w,b1.x,b1.y,b1.z,b1.w};
#pragma unroll
                for (int rr = 0; rr < 8; rr++)
#pragma unroll
                    for (int cc = 0; cc < 8; cc++)
                        acc[rr][cc] += a[rr]*b[cc];
            }
        }

        // ---- epilogue: node = tile*16 + ty, k = rr, cols = tx*4..+3 and 64+tx*4..+3
        int n = tile*TN + ty;
        const float* xrp = x + n*128;
        float4 xv0 = *(const float4*)(xrp + tx*4);
        float4 xv1 = *(const float4*)(xrp + 64 + tx*4);
        float xr[8] = {xv0.x,xv0.y,xv0.z,xv0.w,xv1.x,xv1.y,xv1.z,xv1.w};

        float px = 0.f, p[8];
#pragma unroll
        for (int cc = 0; cc < 8; cc++) {
            int col = (cc < 4) ? tx*4 + cc : 64 + tx*4 + (cc-4);
            px += xr[cc] * qvs[col];
        }
#pragma unroll
        for (int rr = 0; rr < 8; rr++) {
            float s = 0.f;
#pragma unroll
            for (int cc = 0; cc < 8; cc++) {
                int col = (cc < 4) ? tx*4 + cc : 64 + tx*4 + (cc-4);
                s += acc[rr][cc] * Vfs[col];
            }
            p[rr] = s;
        }
#pragma unroll
        for (int m = 1; m < 16; m <<= 1) {
            px += __shfl_xor_sync(0xffffffffu, px, m);
#pragma unroll
            for (int rr = 0; rr < 8; rr++)
                p[rr] += __shfl_xor_sync(0xffffffffu, p[rr], m);
        }
        float sc[8], mx = -1e30f;
#pragma unroll
        for (int rr = 0; rr < 8; rr++) { sc[rr] = tanhf(px + p[rr]); mx = fmaxf(mx, sc[rr]); }
        float ex[8], se = 0.f;
#pragma unroll
        for (int rr = 0; rr < 8; rr++) { ex[rr] = expf(sc[rr] - mx); se += ex[rr]; }
        float inv = 1.f / se;

        int etv[8]; float sume = 0.f;
#pragma unroll
        for (int rr = 0; rr < 8; rr++) { etv[rr] = etype[n*8 + rr]; sume += (float)etv[rr]; }
        float modify = sume * 0.125f;

        float sA[8], sB[8];
#pragma unroll
        for (int cc = 0; cc < 8; cc++) { sA[cc] = 0.f; sB[cc] = 0.f; }
#pragma unroll
        for (int rr = 0; rr < 8; rr++) {
            float w  = ex[rr] * inv;
            float ef = (float)etv[rr];
            float c1 = w * (1.f - modify) * ef;
            float c0 = w * modify * (1.f - ef);
#pragma unroll
            for (int cc = 0; cc < 8; cc++) {
                sA[cc] += c1 * acc[rr][cc];
                sB[cc] += c0 * acc[rr][cc];
            }
        }
        float* Zr = g_Z + (size_t)n * 384;
        *(float4*)(Zr + tx*4)         = make_float4(sB[0],sB[1],sB[2],sB[3]);
        *(float4*)(Zr + 64 + tx*4)    = make_float4(sB[4],sB[5],sB[6],sB[7]);
        *(float4*)(Zr + 128 + tx*4)   = make_float4(sA[0],sA[1],sA[2],sA[3]);
        *(float4*)(Zr + 192 + tx*4)   = make_float4(sA[4],sA[5],sA[6],sA[7]);
        *(float4*)(Zr + 256 + tx*4)   = xv0;
        *(float4*)(Zr + 320 + tx*4)   = xv1;
    }
}

// ---------------- K2B: f = sigmoid(h_mail @ (e ? Of : Zf)); c_red = sum_k f*c_mail ----------------
#define K2B_SMEM ((2*128*128 + 32*132) * 4)
__global__ void __launch_bounds__(256, 1)
k2b(const float* __restrict__ hmail, const float* __restrict__ cmail,
    const float* __restrict__ Of, const float* __restrict__ Zf,
    const int* __restrict__ etype) {
    extern __shared__ float sm[];
    float* Os = sm;
    float* Zs = Os + 128*128;
    float* As = Zs + 128*128;
    const int tid = threadIdx.x, tx = tid & 15, ty = tid >> 4;

    for (int i = tid; i < 128*128/4; i += 256) {
        ((float4*)Os)[i] = ((const float4*)Of)[i];
        ((float4*)Zs)[i] = ((const float4*)Zf)[i];
    }
    __syncthreads();

    for (int tile = blockIdx.x; tile < NTILES; tile += gridDim.x) {
        int n = tile*TN + ty;
        bool sel[8];
#pragma unroll
        for (int rr = 0; rr < 8; rr++) sel[rr] = (etype[n*8 + rr] != 0);

        float acc[8][8];
#pragma unroll
        for (int a = 0; a < 8; a++)
#pragma unroll
            for (int b = 0; b < 8; b++) acc[a][b] = 0.f;

        const float* At = hmail + (size_t)tile * (128*128);
        for (int kb = 0; kb < 128; kb += 32) {
            __syncthreads();
            {
                int cg = tid & 7, r0 = tid >> 3;
#pragma unroll
                for (int p = 0; p < 4; p++) {
                    int r = r0 + p*32;
                    float4 v = *(const float4*)(At + r*128 + kb + cg*4);
                    As[(cg*4+0)*132 + r] = v.x;
                    As[(cg*4+1)*132 + r] = v.y;
                    As[(cg*4+2)*132 + r] = v.z;
                    As[(cg*4+3)*132 + r] = v.w;
                }
            }
            __syncthreads();
#pragma unroll 4
            for (int kk = 0; kk < 32; kk++) {
                float4 a0 = *(const float4*)(As + kk*132 + ty*8);
                float4 a1 = *(const float4*)(As + kk*132 + ty*8 + 4);
                float4 o0 = *(const float4*)(Os + (kb+kk)*128 + tx*4);
                float4 o1 = *(const float4*)(Os + (kb+kk)*128 + 64 + tx*4);
                float4 z0 = *(const float4*)(Zs + (kb+kk)*128 + tx*4);
                float4 z1 = *(const float4*)(Zs + (kb+kk)*128 + 64 + tx*4);
                float a[8]  = {a0.x,a0.y,a0.z,a0.w,a1.x,a1.y,a1.z,a1.w};
                float bo[8] = {o0.x,o0.y,o0.z,o0.w,o1.x,o1.y,o1.z,o1.w};
                float bz[8] = {z0.x,z0.y,z0.z,z0.w,z1.x,z1.y,z1.z,z1.w};
#pragma unroll
                for (int rr = 0; rr < 8; rr++)
#pragma unroll
                    for (int cc = 0; cc < 8; cc++) {
                        float b = sel[rr] ? bo[cc] : bz[cc];
                        acc[rr][cc] += a[rr]*b;
                    }
            }
        }
        // epilogue: c_red
        float cr[8];
#pragma unroll
        for (int cc = 0; cc < 8; cc++) cr[cc] = 0.f;
#pragma unroll
        for (int rr = 0; rr < 8; rr++) {
            const float* cm = cmail + ((size_t)n*8 + rr) * 128;
            float4 c0 = *(const float4*)(cm + tx*4);
            float4 c1 = *(const float4*)(cm + 64 + tx*4);
            float cv[8] = {c0.x,c0.y,c0.z,c0.w,c1.x,c1.y,c1.z,c1.w};
#pragma unroll
            for (int cc = 0; cc < 8; cc++) {
                float f = 1.f / (1.f + expf(-acc[rr][cc]));
                cr[cc] += f * cv[cc];
            }
        }
        float* cp = g_cred + (size_t)n * 128;
        *(float4*)(cp + tx*4)      = make_float4(cr[0],cr[1],cr[2],cr[3]);
        *(float4*)(cp + 64 + tx*4) = make_float4(cr[4],cr[5],cr[6],cr[7]);
    }
}

// ---------------- K3a: IOU = Z @ G + biou ----------------
__global__ void __launch_bounds__(256, 2)
k3a(const float* __restrict__ biou) {
    __shared__ float As[32*132];
    __shared__ float Bs[32*128];
    const int tid = threadIdx.x, tx = tid & 15, ty = tid >> 4;
    const int bx = blockIdx.x;       // 0..2 col tile
    const int by = blockIdx.y;       // 0..390 row tile
    const float* A = g_Z + (size_t)by * 128 * 384;

    float acc[8][8];
#pragma unroll
    for (int a = 0; a < 8; a++)
#pragma unroll
        for (int b = 0; b < 8; b++) acc[a][b] = 0.f;

    for (int kb = 0; kb < 384; kb += 32) {
        __syncthreads();
        {
            int cg = tid & 7, r0 = tid >> 3;
#pragma unroll
            for (int p = 0; p < 4; p++) {
                int r = r0 + p*32;
                float4 v = *(const float4*)(A + (size_t)r*384 + kb + cg*4);
                As[(cg*4+0)*132 + r] = v.x;
                As[(cg*4+1)*132 + r] = v.y;
                As[(cg*4+2)*132 + r] = v.z;
                As[(cg*4+3)*132 + r] = v.w;
            }
        }
        {
#pragma unroll
            for (int it = 0; it < 4; it++) {
                int flat = it*256 + tid;
                int kk = flat >> 5, j4 = flat & 31;
                *(float4*)(Bs + kk*128 + j4*4) =
                    *(const float4*)(g_G + (size_t)(kb+kk)*384 + bx*128 + j4*4);
            }
        }
        __syncthreads();
#pragma unroll 8
        for (int kk = 0; kk < 32; kk++) {
            float4 a0 = *(const float4*)(As + kk*132 + ty*8);
            float4 a1 = *(const float4*)(As + kk*132 + ty*8 + 4);
            float4 b0 = *(const float4*)(Bs + kk*128 + tx*4);
            float4 b1 = *(const float4*)(Bs + kk*128 + 64 + tx*4);
            float a[8] = {a0.x,a0.y,a0.z,a0.w,a1.x,a1.y,a1.z,a1.w};
            float b[8] = {b0.x,b0.y,b0.z,b0.w,b1.x,b1.y,b1.z,b1.w};
#pragma unroll
            for (int rr = 0; rr < 8; rr++)
#pragma unroll
                for (int cc = 0; cc < 8; cc++)
                    acc[rr][cc] += a[rr]*b[cc];
        }
    }
    int jb = bx*128;
    float bi0[4], bi1[4];
#pragma unroll
    for (int q = 0; q < 4; q++) {
        bi0[q] = biou[jb + tx*4 + q];
        bi1[q] = biou[jb + 64 + tx*4 + q];
    }
#pragma unroll
    for (int rr = 0; rr < 8; rr++) {
        size_t row = (size_t)by*128 + ty*8 + rr;
        float* op = g_IOU + row*384 + jb;
        *(float4*)(op + tx*4) = make_float4(acc[rr][0]+bi0[0], acc[rr][1]+bi0[1],
                                            acc[rr][2]+bi0[2], acc[rr][3]+bi0[3]);
        *(float4*)(op + 64 + tx*4) = make_float4(acc[rr][4]+bi1[0], acc[rr][5]+bi1[1],
                                                 acc[rr][6]+bi1[2], acc[rr][7]+bi1[3]);
    }
}

// ---------------- K3b: gates -> out ----------------
__global__ void k3b(float* __restrict__ out) {
    int idx = blockIdx.x * blockDim.x + threadIdx.x;   // (n, j4), 50000*32 total
    if (idx >= NN*32) return;
    int n = idx >> 5;
    int j = (idx & 31) * 4;
    const float* r = g_IOU + (size_t)n * 384;
    float4 iv = *(const float4*)(r + j);
    float4 ov = *(const float4*)(r + 128 + j);
    float4 uv = *(const float4*)(r + 256 + j);
    float4 cr = *(const float4*)(g_cred + (size_t)n*128 + j);
    float4 hc, cc;
    {
        float ig, og, ug, c, h;
        ig = 1.f/(1.f+expf(-iv.x)); og = 1.f/(1.f+expf(-ov.x)); ug = tanhf(uv.x);
        c = ig*ug + cr.x; h = og*tanhf(c); hc.x = h; cc.x = c;
        ig = 1.f/(1.f+expf(-iv.y)); og = 1.f/(1.f+expf(-ov.y)); ug = tanhf(uv.y);
        c = ig*ug + cr.y; h = og*tanhf(c); hc.y = h; cc.y = c;
        ig = 1.f/(1.f+expf(-iv.z)); og = 1.f/(1.f+expf(-ov.z)); ug = tanhf(uv.z);
        c = ig*ug + cr.z; h = og*tanhf(c); hc.z = h; cc.z = c;
        ig = 1.f/(1.f+expf(-iv.w)); og = 1.f/(1.f+expf(-ov.w)); ug = tanhf(uv.w);
        c = ig*ug + cr.w; h = og*tanhf(c); hc.w = h; cc.w = c;
    }
    *(float4*)(out + (size_t)n*128 + j) = hc;
    *(float4*)(out + (size_t)NN*128 + (size_t)n*128 + j) = cc;
}

// ---------------- launcher ----------------
extern "C" void kernel_launch(void* const* d_in, const int* in_sizes, int n_in,
                              void* d_out, int out_size) {
    const float* x      = (const float*)d_in[0];
    const float* h_mail = (const float*)d_in[1];
    const float* c_mail = (const float*)d_in[2];
    const float* Wiou   = (const float*)d_in[3];
    const float* Uiou   = (const float*)d_in[4];
    const float* biou   = (const float*)d_in[5];
    const float* Of     = (const float*)d_in[6];
    const float* Zf     = (const float*)d_in[7];
    const float* Qf     = (const float*)d_in[8];
    const float* Kf     = (const float*)d_in[9];
    const float* vf     = (const float*)d_in[10];
    const float* Wa     = (const float*)d_in[11];
    const float* Wd     = (const float*)d_in[12];
    const float* Vf     = (const float*)d_in[13];
    const int*   etype  = (const int*)d_in[14];
    float* out = (float*)d_out;

    cudaFuncSetAttribute(k2a, cudaFuncAttributeMaxDynamicSharedMemorySize, K2A_SMEM);
    cudaFuncSetAttribute(k2b, cudaFuncAttributeMaxDynamicSharedMemorySize, K2B_SMEM);

    k1a<<<384, 256>>>(Wa, Wd, Uiou);
    k1b<<<577, 256>>>(vf, Wiou, Qf, Vf);
    k2a<<<296, 256, K2A_SMEM>>>(x, h_mail, Kf, Vf, etype);
    k2b<<<148, 256, K2B_SMEM>>>(h_mail, c_mail, Of, Zf, etype);
    k3a<<<dim3(3, 391), 256>>>(biou);
    k3b<<<6250, 256>>>(out);
}

// round 7
// speedup vs baseline: 1.3251x; 1.3251x over previous
#include <cuda_runtime.h>
#include <cuda_bf16.h>
#include <math.h>

#define NN 50000
#define HH 128
#define NPAD 50048            // 391*128, padded rows for K3 GEMM (zero-init)
#define TN 16                 // nodes per tile (16*8 = 128 rows)
#define NTILES (NN/TN)        // 3125

// ---------------- scratch (__device__ globals; zero-initialized) ----------------
__device__ float g_T[2*128*384];              // Wd@U0 | Wa@U1
__device__ float g_G[384*384];                // [vf@Wd@U0 ; vf@Wa@U1 ; Wiou]
__device__ float g_qv[128];                   // Qf @ Vf
__device__ float g_Z[(size_t)NPAD*384];       // [sB | sA | x]
__device__ float g_IOU[(size_t)NPAD*384];
__device__ float g_cred[(size_t)NN*128];

// ================= helpers =================
__device__ __forceinline__ unsigned smem_u32(const void* p) {
    unsigned a;
    asm("{ .reg .u64 t; cvta.to.shared.u64 t, %1; cvt.u32.u64 %0, t; }" : "=r"(a) : "l"(p));
    return a;
}

__device__ __forceinline__ void ldsm4(unsigned r[4], unsigned addr) {
    asm volatile("ldmatrix.sync.aligned.m8n8.x4.shared.b16 {%0,%1,%2,%3}, [%4];"
                 : "=r"(r[0]), "=r"(r[1]), "=r"(r[2]), "=r"(r[3]) : "r"(addr));
}

__device__ __forceinline__ void mma16816(float c[4], const unsigned a[4],
                                         unsigned b0, unsigned b1) {
    asm volatile("mma.sync.aligned.m16n8k16.row.col.f32.bf16.bf16.f32 "
                 "{%0,%1,%2,%3}, {%4,%5,%6,%7}, {%8,%9}, {%0,%1,%2,%3};"
                 : "+f"(c[0]), "+f"(c[1]), "+f"(c[2]), "+f"(c[3])
                 : "r"(a[0]), "r"(a[1]), "r"(a[2]), "r"(a[3]), "r"(b0), "r"(b1));
}

// fp32 -> bf16 hi/lo split, 2 elements packed per word
__device__ __forceinline__ void split2(float a, float b, unsigned& hi, unsigned& lo) {
    __nv_bfloat16 ha = __float2bfloat16_rn(a);
    __nv_bfloat16 hb = __float2bfloat16_rn(b);
    __nv_bfloat16 la = __float2bfloat16_rn(a - __bfloat162float(ha));
    __nv_bfloat16 lb = __float2bfloat16_rn(b - __bfloat162float(hb));
    hi = ((unsigned)__bfloat16_as_ushort(hb) << 16) | (unsigned)__bfloat16_as_ushort(ha);
    lo = ((unsigned)__bfloat16_as_ushort(lb) << 16) | (unsigned)__bfloat16_as_ushort(la);
}

// ---------------- K1a: T0 = Wd@U0, T1 = Wa@U1 ----------------
__global__ void k1a(const float* __restrict__ Wa, const float* __restrict__ Wd,
                    const float* __restrict__ Uiou) {
    int idx = blockIdx.x * blockDim.x + threadIdx.x;
    if (idx >= 2*128*384) return;
    int which = idx / (128*384);
    int rem   = idx - which*(128*384);
    int m = rem / 384, j = rem - m*384;
    const float* W = which ? Wa : Wd;
    const float* U = Uiou + which*(128*384);
    float s = 0.f;
#pragma unroll 8
    for (int z = 0; z < 128; z++) s += W[m*128+z] * U[z*384+j];
    g_T[idx] = s;
}

// ---------------- K1b: G rows; qv = Qf@Vf ----------------
__global__ void k1b(const float* __restrict__ vf, const float* __restrict__ Wiou,
                    const float* __restrict__ Qf, const float* __restrict__ Vf) {
    int idx = blockIdx.x * blockDim.x + threadIdx.x;
    if (idx < 2*128*384) {
        int which = idx / (128*384);
        int rem   = idx - which*(128*384);
        int m = rem / 384, j = rem - m*384;
        const float* T = g_T + which*(128*384);
        float s = 0.f;
#pragma unroll 8
        for (int z = 0; z < 128; z++) s += vf[m*128+z] * T[z*384+j];
        g_G[idx] = s;
    } else if (idx < 3*128*384) {
        int rem = idx - 2*128*384;
        g_G[idx] = Wiou[rem];
    } else if (idx < 3*128*384 + 128) {
        int m = idx - 3*128*384;
        float s = 0.f;
#pragma unroll 8
        for (int j = 0; j < 128; j++) s += Qf[m*128+j] * Vf[j];
        g_qv[m] = s;
    }
}

// ---------------- K2A: hk = h_mail@Kf, scores, softmax, weighted sums -> Z ----------------
#define K2A_SMEM ((128*128 + 32*132 + 128 + 128) * 4)
__global__ void __launch_bounds__(256, 2)
k2a(const float* __restrict__ x, const float* __restrict__ hmail,
    const float* __restrict__ Kf, const float* __restrict__ Vf,
    const int* __restrict__ etype) {
    extern __shared__ float sm[];
    float* Bs  = sm;
    float* As  = Bs + 128*128;
    float* Vfs = As + 32*132;
    float* qvs = Vfs + 128;
    const int tid = threadIdx.x, tx = tid & 15, ty = tid >> 4;

    for (int i = tid; i < 128*128/4; i += 256)
        ((float4*)Bs)[i] = ((const float4*)Kf)[i];
    if (tid < 128) { Vfs[tid] = Vf[tid]; qvs[tid] = g_qv[tid]; }
    __syncthreads();

    for (int tile = blockIdx.x; tile < NTILES; tile += gridDim.x) {
        float acc[8][8];
#pragma unroll
        for (int a = 0; a < 8; a++)
#pragma unroll
            for (int b = 0; b < 8; b++) acc[a][b] = 0.f;

        const float* At = hmail + (size_t)tile * (128*128);
        for (int kb = 0; kb < 128; kb += 32) {
            __syncthreads();
            {
                int cg = tid & 7, r0 = tid >> 3;
#pragma unroll
                for (int p = 0; p < 4; p++) {
                    int r = r0 + p*32;
                    float4 v = *(const float4*)(At + r*128 + kb + cg*4);
                    As[(cg*4+0)*132 + r] = v.x;
                    As[(cg*4+1)*132 + r] = v.y;
                    As[(cg*4+2)*132 + r] = v.z;
                    As[(cg*4+3)*132 + r] = v.w;
                }
            }
            __syncthreads();
#pragma unroll 8
            for (int kk = 0; kk < 32; kk++) {
                float4 a0 = *(const float4*)(As + kk*132 + ty*8);
                float4 a1 = *(const float4*)(As + kk*132 + ty*8 + 4);
                float4 b0 = *(const float4*)(Bs + (kb+kk)*128 + tx*4);
                float4 b1 = *(const float4*)(Bs + (kb+kk)*128 + 64 + tx*4);
                float a[8] = {a0.x,a0.y,a0.z,a0.w,a1.x,a1.y,a1.z,a1.w};
                float b[8] = {b0.x,b0.y,b0.z,b0.w,b1.x,b1.y,b1.z,b1.w};
#pragma unroll
                for (int rr = 0; rr < 8; rr++)
#pragma unroll
                    for (int cc = 0; cc < 8; cc++)
                        acc[rr][cc] += a[rr]*b[cc];
            }
        }

        int n = tile*TN + ty;
        const float* xrp = x + n*128;
        float4 xv0 = *(const float4*)(xrp + tx*4);
        float4 xv1 = *(const float4*)(xrp + 64 + tx*4);
        float xr[8] = {xv0.x,xv0.y,xv0.z,xv0.w,xv1.x,xv1.y,xv1.z,xv1.w};

        float px = 0.f, p[8];
#pragma unroll
        for (int cc = 0; cc < 8; cc++) {
            int col = (cc < 4) ? tx*4 + cc : 64 + tx*4 + (cc-4);
            px += xr[cc] * qvs[col];
        }
#pragma unroll
        for (int rr = 0; rr < 8; rr++) {
            float s = 0.f;
#pragma unroll
            for (int cc = 0; cc < 8; cc++) {
                int col = (cc < 4) ? tx*4 + cc : 64 + tx*4 + (cc-4);
                s += acc[rr][cc] * Vfs[col];
            }
            p[rr] = s;
        }
#pragma unroll
        for (int m = 1; m < 16; m <<= 1) {
            px += __shfl_xor_sync(0xffffffffu, px, m);
#pragma unroll
            for (int rr = 0; rr < 8; rr++)
                p[rr] += __shfl_xor_sync(0xffffffffu, p[rr], m);
        }
        float sc[8], mx = -1e30f;
#pragma unroll
        for (int rr = 0; rr < 8; rr++) { sc[rr] = tanhf(px + p[rr]); mx = fmaxf(mx, sc[rr]); }
        float ex[8], se = 0.f;
#pragma unroll
        for (int rr = 0; rr < 8; rr++) { ex[rr] = expf(sc[rr] - mx); se += ex[rr]; }
        float inv = 1.f / se;

        int etv[8]; float sume = 0.f;
#pragma unroll
        for (int rr = 0; rr < 8; rr++) { etv[rr] = etype[n*8 + rr]; sume += (float)etv[rr]; }
        float modify = sume * 0.125f;

        float sA[8], sB[8];
#pragma unroll
        for (int cc = 0; cc < 8; cc++) { sA[cc] = 0.f; sB[cc] = 0.f; }
#pragma unroll
        for (int rr = 0; rr < 8; rr++) {
            float w  = ex[rr] * inv;
            float ef = (float)etv[rr];
            float c1 = w * (1.f - modify) * ef;
            float c0 = w * modify * (1.f - ef);
#pragma unroll
            for (int cc = 0; cc < 8; cc++) {
                sA[cc] += c1 * acc[rr][cc];
                sB[cc] += c0 * acc[rr][cc];
            }
        }
        float* Zr = g_Z + (size_t)n * 384;
        *(float4*)(Zr + tx*4)         = make_float4(sB[0],sB[1],sB[2],sB[3]);
        *(float4*)(Zr + 64 + tx*4)    = make_float4(sB[4],sB[5],sB[6],sB[7]);
        *(float4*)(Zr + 128 + tx*4)   = make_float4(sA[0],sA[1],sA[2],sA[3]);
        *(float4*)(Zr + 192 + tx*4)   = make_float4(sA[4],sA[5],sA[6],sA[7]);
        *(float4*)(Zr + 256 + tx*4)   = xv0;
        *(float4*)(Zr + 320 + tx*4)   = xv1;
    }
}

// ---------------- K2B (mma.sync bf16, 3-term split precision) ----------------
// acc[row][j] = hm[row] @ Zf[:,j] + (e[row]*hm[row]) @ D[:,j],  D = Of - Zf
// terms: Ah@Zh + Ah@Zl + Al@Zh + Aeh@Dh + Aeh@Dl + Ael@Dh
// SMEM: 4 x 32KB weights (Zh,Zl,Dh,Dl as [n][k] bf16) | 4 x 16KB A chunk (Ah,Al,Aeh,Ael)
#define K2B_SMEM (4*32768 + 4*16384)
__global__ void __launch_bounds__(256, 1)
k2b(const float* __restrict__ hmail, const float* __restrict__ cmail,
    const float* __restrict__ Of, const float* __restrict__ Zf,
    const int* __restrict__ etype) {
    extern __shared__ char smc[];
    const unsigned smb = smem_u32(smc);
    const int tid = threadIdx.x, wid = tid >> 5, lane = tid & 31;
    const unsigned AB = smb + 131072;   // A tile base

    // weight prep: W[n][k] = Wsrc[k][n]; bf16 hi/lo; XOR-swizzled 16B units (row stride 256B)
    for (int idx = tid; idx < 128*128; idx += 256) {
        int n = idx & 127, k = idx >> 7;
        float zf = Zf[k*128 + n];
        float d  = Of[k*128 + n] - zf;
        __nv_bfloat16 zh = __float2bfloat16_rn(zf);
        __nv_bfloat16 zl = __float2bfloat16_rn(zf - __bfloat162float(zh));
        __nv_bfloat16 dh = __float2bfloat16_rn(d);
        __nv_bfloat16 dl = __float2bfloat16_rn(d - __bfloat162float(dh));
        unsigned off = (unsigned)(n*256 + ((2*k) ^ ((n & 7) << 4)));
        *(__nv_bfloat16*)(smc + 0*32768 + off) = zh;
        *(__nv_bfloat16*)(smc + 1*32768 + off) = zl;
        *(__nv_bfloat16*)(smc + 2*32768 + off) = dh;
        *(__nv_bfloat16*)(smc + 3*32768 + off) = dl;
    }
    __syncthreads();

    for (int tile = blockIdx.x; tile < NTILES; tile += gridDim.x) {
        const size_t rbase = (size_t)tile * 128;

        float acc[8][2][4];
#pragma unroll
        for (int g = 0; g < 8; g++)
#pragma unroll
            for (int s = 0; s < 2; s++)
#pragma unroll
                for (int q = 0; q < 4; q++) acc[g][s][q] = 0.f;

        for (int chunk = 0; chunk < 2; chunk++) {
            // ---- convert A chunk [128 rows x 64 k] -> Ah/Al/Aeh/Ael (rows 128B, swizzled)
            {
                const int row = tid >> 1, halfk = tid & 1;
                unsigned msk = (etype[rbase + row] != 0) ? 0xffffffffu : 0u;
                const float* src = hmail + (rbase + row)*128 + chunk*64 + halfk*32;
                const unsigned rsw = (unsigned)((row & 7) << 4);
#pragma unroll
                for (int i = 0; i < 8; i++) {
                    float4 v = ((const float4*)src)[i];
                    unsigned h0, l0, h1, l1;
                    split2(v.x, v.y, h0, l0);
                    split2(v.z, v.w, h1, l1);
                    int j = halfk*32 + i*4;                       // element index in chunk
                    unsigned bo = (unsigned)(row*128 + ((2*j) ^ rsw));
                    char* p = smc + 131072;
                    *(unsigned*)(p + 0*16384 + bo)     = h0;
                    *(unsigned*)(p + 0*16384 + bo + 4) = h1;
                    *(unsigned*)(p + 1*16384 + bo)     = l0;
                    *(unsigned*)(p + 1*16384 + bo + 4) = l1;
                    *(unsigned*)(p + 2*16384 + bo)     = h0 & msk;
                    *(unsigned*)(p + 2*16384 + bo + 4) = h1 & msk;
                    *(unsigned*)(p + 3*16384 + bo)     = l0 & msk;
                    *(unsigned*)(p + 3*16384 + bo + 4) = l1 & msk;
                }
            }
            __syncthreads();

            // ---- MMA: warp wid owns rows wid*16..wid*16+15, all 128 cols
            {
                const int arow = wid*16 + (lane & 7) + ((lane >> 3) & 1) * 8;
                const unsigned arsw = (unsigned)((arow & 7) << 4);
                const int bn_l = (lane & 7) + (lane >> 4) * 8;
                const int bkb_l = ((lane >> 3) & 1) * 16;
#pragma unroll
                for (int kk = 0; kk < 4; kk++) {
                    unsigned akb = (unsigned)(kk*32 + (lane >> 4) * 16);
                    unsigned aoff = (unsigned)(arow*128) + (akb ^ arsw);
                    unsigned av[4][4];
#pragma unroll
                    for (int ver = 0; ver < 4; ver++)
                        ldsm4(av[ver], AB + ver*16384 + aoff);

                    const int bkb = chunk*128 + kk*32 + bkb_l;
#pragma unroll
                    for (int g = 0; g < 8; g++) {
                        int bn = g*16 + bn_l;
                        unsigned boff = (unsigned)(bn*256) +
                                        ((unsigned)bkb ^ ((unsigned)(bn & 7) << 4));
                        unsigned zh[4], zl[4], dh[4], dl[4];
                        ldsm4(zh, smb + 0*32768 + boff);
                        ldsm4(zl, smb + 1*32768 + boff);
                        ldsm4(dh, smb + 2*32768 + boff);
                        ldsm4(dl, smb + 3*32768 + boff);
#pragma unroll
                        for (int s = 0; s < 2; s++) {
                            unsigned b0z = zh[s*2], b1z = zh[s*2+1];
                            unsigned b0l = zl[s*2], b1l = zl[s*2+1];
                            unsigned b0d = dh[s*2], b1d = dh[s*2+1];
                            unsigned b0e = dl[s*2], b1e = dl[s*2+1];
                            mma16816(acc[g][s], av[0], b0z, b1z);
                            mma16816(acc[g][s], av[1], b0z, b1z);
                            mma16816(acc[g][s], av[0], b0l, b1l);
                            mma16816(acc[g][s], av[2], b0d, b1d);
                            mma16816(acc[g][s], av[3], b0d, b1d);
                            mma16816(acc[g][s], av[2], b0e, b1e);
                        }
                    }
                }
            }
            __syncthreads();   // before next chunk's convert overwrites A tiles
        }

        // ---- epilogue: f = sigmoid(acc); c_red[node] = sum over 8 mail-rows of f*c_mail
        {
            const int rlo = wid*16 + (lane >> 2);       // rows of node0 (local)
            const int rhi = rlo + 8;                    // rows of node1
            const int node0 = tile*TN + wid*2;
            const int cidx = lane & 3;
#pragma unroll
            for (int g = 0; g < 8; g++)
#pragma unroll
                for (int s = 0; s < 2; s++) {
                    int col = g*16 + s*8 + cidx*2;
                    float2 c0 = *(const float2*)(cmail + (rbase + rlo)*128 + col);
                    float2 c1 = *(const float2*)(cmail + (rbase + rhi)*128 + col);
                    float v0 = c0.x / (1.f + expf(-acc[g][s][0]));
                    float v1 = c0.y / (1.f + expf(-acc[g][s][1]));
                    float v2 = c1.x / (1.f + expf(-acc[g][s][2]));
                    float v3 = c1.y / (1.f + expf(-acc[g][s][3]));
#pragma unroll
                    for (int m = 4; m < 32; m <<= 1) {
                        v0 += __shfl_xor_sync(0xffffffffu, v0, m);
                        v1 += __shfl_xor_sync(0xffffffffu, v1, m);
                        v2 += __shfl_xor_sync(0xffffffffu, v2, m);
                        v3 += __shfl_xor_sync(0xffffffffu, v3, m);
                    }
                    if (lane < 4) {
                        int c = g*16 + s*8 + lane*2;
                        *(float2*)(g_cred + (size_t)node0*128 + c) = make_float2(v0, v1);
                    } else if (lane < 8) {
                        int c = g*16 + s*8 + (lane - 4)*2;
                        *(float2*)(g_cred + (size_t)(node0+1)*128 + c) = make_float2(v2, v3);
                    }
                }
        }
    }
}

// ---------------- K3a: IOU = Z @ G + biou ----------------
__global__ void __launch_bounds__(256, 2)
k3a(const float* __restrict__ biou) {
    __shared__ float As[32*132];
    __shared__ float Bs[32*128];
    const int tid = threadIdx.x, tx = tid & 15, ty = tid >> 4;
    const int bx = blockIdx.x;
    const int by = blockIdx.y;
    const float* A = g_Z + (size_t)by * 128 * 384;

    float acc[8][8];
#pragma unroll
    for (int a = 0; a < 8; a++)
#pragma unroll
        for (int b = 0; b < 8; b++) acc[a][b] = 0.f;

    for (int kb = 0; kb < 384; kb += 32) {
        __syncthreads();
        {
            int cg = tid & 7, r0 = tid >> 3;
#pragma unroll
            for (int p = 0; p < 4; p++) {
                int r = r0 + p*32;
                float4 v = *(const float4*)(A + (size_t)r*384 + kb + cg*4);
                As[(cg*4+0)*132 + r] = v.x;
                As[(cg*4+1)*132 + r] = v.y;
                As[(cg*4+2)*132 + r] = v.z;
                As[(cg*4+3)*132 + r] = v.w;
            }
        }
        {
#pragma unroll
            for (int it = 0; it < 4; it++) {
                int flat = it*256 + tid;
                int kk = flat >> 5, j4 = flat & 31;
                *(float4*)(Bs + kk*128 + j4*4) =
                    *(const float4*)(g_G + (size_t)(kb+kk)*384 + bx*128 + j4*4);
            }
        }
        __syncthreads();
#pragma unroll 8
        for (int kk = 0; kk < 32; kk++) {
            float4 a0 = *(const float4*)(As + kk*132 + ty*8);
            float4 a1 = *(const float4*)(As + kk*132 + ty*8 + 4);
            float4 b0 = *(const float4*)(Bs + kk*128 + tx*4);
            float4 b1 = *(const float4*)(Bs + kk*128 + 64 + tx*4);
            float a[8] = {a0.x,a0.y,a0.z,a0.w,a1.x,a1.y,a1.z,a1.w};
            float b[8] = {b0.x,b0.y,b0.z,b0.w,b1.x,b1.y,b1.z,b1.w};
#pragma unroll
            for (int rr = 0; rr < 8; rr++)
#pragma unroll
                for (int cc = 0; cc < 8; cc++)
                    acc[rr][cc] += a[rr]*b[cc];
        }
    }
    int jb = bx*128;
    float bi0[4], bi1[4];
#pragma unroll
    for (int q = 0; q < 4; q++) {
        bi0[q] = biou[jb + tx*4 + q];
        bi1[q] = biou[jb + 64 + tx*4 + q];
    }
#pragma unroll
    for (int rr = 0; rr < 8; rr++) {
        size_t row = (size_t)by*128 + ty*8 + rr;
        float* op = g_IOU + row*384 + jb;
        *(float4*)(op + tx*4) = make_float4(acc[rr][0]+bi0[0], acc[rr][1]+bi0[1],
                                            acc[rr][2]+bi0[2], acc[rr][3]+bi0[3]);
        *(float4*)(op + 64 + tx*4) = make_float4(acc[rr][4]+bi1[0], acc[rr][5]+bi1[1],
                                                 acc[rr][6]+bi1[2], acc[rr][7]+bi1[3]);
    }
}

// ---------------- K3b: gates -> out ----------------
__global__ void k3b(float* __restrict__ out) {
    int idx = blockIdx.x * blockDim.x + threadIdx.x;
    if (idx >= NN*32) return;
    int n = idx >> 5;
    int j = (idx & 31) * 4;
    const float* r = g_IOU + (size_t)n * 384;
    float4 iv = *(const float4*)(r + j);
    float4 ov = *(const float4*)(r + 128 + j);
    float4 uv = *(const float4*)(r + 256 + j);
    float4 cr = *(const float4*)(g_cred + (size_t)n*128 + j);
    float4 hc, cc;
    {
        float ig, og, ug, c, h;
        ig = 1.f/(1.f+expf(-iv.x)); og = 1.f/(1.f+expf(-ov.x)); ug = tanhf(uv.x);
        c = ig*ug + cr.x; h = og*tanhf(c); hc.x = h; cc.x = c;
        ig = 1.f/(1.f+expf(-iv.y)); og = 1.f/(1.f+expf(-ov.y)); ug = tanhf(uv.y);
        c = ig*ug + cr.y; h = og*tanhf(c); hc.y = h; cc.y = c;
        ig = 1.f/(1.f+expf(-iv.z)); og = 1.f/(1.f+expf(-ov.z)); ug = tanhf(uv.z);
        c = ig*ug + cr.z; h = og*tanhf(c); hc.z = h; cc.z = c;
        ig = 1.f/(1.f+expf(-iv.w)); og = 1.f/(1.f+expf(-ov.w)); ug = tanhf(uv.w);
        c = ig*ug + cr.w; h = og*tanhf(c); hc.w = h; cc.w = c;
    }
    *(float4*)(out + (size_t)n*128 + j) = hc;
    *(float4*)(out + (size_t)NN*128 + (size_t)n*128 + j) = cc;
}

// ---------------- launcher ----------------
extern "C" void kernel_launch(void* const* d_in, const int* in_sizes, int n_in,
                              void* d_out, int out_size) {
    const float* x      = (const float*)d_in[0];
    const float* h_mail = (const float*)d_in[1];
    const float* c_mail = (const float*)d_in[2];
    const float* Wiou   = (const float*)d_in[3];
    const float* Uiou   = (const float*)d_in[4];
    const float* biou   = (const float*)d_in[5];
    const float* Of     = (const float*)d_in[6];
    const float* Zf     = (const float*)d_in[7];
    const float* Qf     = (const float*)d_in[8];
    const float* Kf     = (const float*)d_in[9];
    const float* vf     = (const float*)d_in[10];
    const float* Wa     = (const float*)d_in[11];
    const float* Wd     = (const float*)d_in[12];
    const float* Vf     = (const float*)d_in[13];
    const int*   etype  = (const int*)d_in[14];
    float* out = (float*)d_out;

    cudaFuncSetAttribute(k2a, cudaFuncAttributeMaxDynamicSharedMemorySize, K2A_SMEM);
    cudaFuncSetAttribute(k2b, cudaFuncAttributeMaxDynamicSharedMemorySize, K2B_SMEM);

    k1a<<<384, 256>>>(Wa, Wd, Uiou);
    k1b<<<577, 256>>>(vf, Wiou, Qf, Vf);
    k2a<<<296, 256, K2A_SMEM>>>(x, h_mail, Kf, Vf, etype);
    k2b<<<148, 256, K2B_SMEM>>>(h_mail, c_mail, Of, Zf, etype);
    k3a<<<dim3(3, 391), 256>>>(biou);
    k3b<<<6250, 256>>>(out);
}

// round 8
// speedup vs baseline: 1.6478x; 1.2435x over previous
#include <cuda_runtime.h>
#include <cuda_bf16.h>
#include <math.h>

#define NN 50000
#define HH 128
#define NPAD 50048            // 391*128, padded rows for K3 GEMM (zero-init)
#define TN 16                 // nodes per tile (16*8 = 128 rows)
#define NTILES (NN/TN)        // 3125

// ---------------- scratch (__device__ globals; zero-initialized) ----------------
__device__ float g_T[2*128*384];              // Wd@U0 | Wa@U1
__device__ float g_G[384*384];                // [vf@Wd@U0 ; vf@Wa@U1 ; Wiou]
__device__ float g_qv[128];                   // Qf @ Vf
__device__ float g_px[NN];                    // x . qv  (per node)
__device__ float g_Z[(size_t)NPAD*384];       // [sB | sA | x]
__device__ float g_IOU[(size_t)NPAD*384];
__device__ float g_cred[(size_t)NN*128];

// ================= helpers =================
__device__ __forceinline__ unsigned smem_u32(const void* p) {
    unsigned a;
    asm("{ .reg .u64 t; cvta.to.shared.u64 t, %1; cvt.u32.u64 %0, t; }" : "=r"(a) : "l"(p));
    return a;
}

__device__ __forceinline__ void ldsm4(unsigned r[4], unsigned addr) {
    asm volatile("ldmatrix.sync.aligned.m8n8.x4.shared.b16 {%0,%1,%2,%3}, [%4];"
                 : "=r"(r[0]), "=r"(r[1]), "=r"(r[2]), "=r"(r[3]) : "r"(addr));
}

__device__ __forceinline__ void mma16816(float c[4], const unsigned a[4],
                                         unsigned b0, unsigned b1) {
    asm volatile("mma.sync.aligned.m16n8k16.row.col.f32.bf16.bf16.f32 "
                 "{%0,%1,%2,%3}, {%4,%5,%6,%7}, {%8,%9}, {%0,%1,%2,%3};"
                 : "+f"(c[0]), "+f"(c[1]), "+f"(c[2]), "+f"(c[3])
                 : "r"(a[0]), "r"(a[1]), "r"(a[2]), "r"(a[3]), "r"(b0), "r"(b1));
}

// fp32 -> bf16 hi/lo split, 2 elements packed per word
__device__ __forceinline__ void split2(float a, float b, unsigned& hi, unsigned& lo) {
    __nv_bfloat16 ha = __float2bfloat16_rn(a);
    __nv_bfloat16 hb = __float2bfloat16_rn(b);
    __nv_bfloat16 la = __float2bfloat16_rn(a - __bfloat162float(ha));
    __nv_bfloat16 lb = __float2bfloat16_rn(b - __bfloat162float(hb));
    hi = ((unsigned)__bfloat16_as_ushort(hb) << 16) | (unsigned)__bfloat16_as_ushort(ha);
    lo = ((unsigned)__bfloat16_as_ushort(lb) << 16) | (unsigned)__bfloat16_as_ushort(la);
}

__device__ __forceinline__ float shflr(float v, int m) {
    return __shfl_xor_sync(0xffffffffu, v, m);
}

// ---------------- K1a: T0 = Wd@U0, T1 = Wa@U1 ----------------
__global__ void k1a(const float* __restrict__ Wa, const float* __restrict__ Wd,
                    const float* __restrict__ Uiou) {
    int idx = blockIdx.x * blockDim.x + threadIdx.x;
    if (idx >= 2*128*384) return;
    int which = idx / (128*384);
    int rem   = idx - which*(128*384);
    int m = rem / 384, j = rem - m*384;
    const float* W = which ? Wa : Wd;
    const float* U = Uiou + which*(128*384);
    float s = 0.f;
#pragma unroll 8
    for (int z = 0; z < 128; z++) s += W[m*128+z] * U[z*384+j];
    g_T[idx] = s;
}

// ---------------- K1b: G rows; qv = Qf@Vf ----------------
__global__ void k1b(const float* __restrict__ vf, const float* __restrict__ Wiou,
                    const float* __restrict__ Qf, const float* __restrict__ Vf) {
    int idx = blockIdx.x * blockDim.x + threadIdx.x;
    if (idx < 2*128*384) {
        int which = idx / (128*384);
        int rem   = idx - which*(128*384);
        int m = rem / 384, j = rem - m*384;
        const float* T = g_T + which*(128*384);
        float s = 0.f;
#pragma unroll 8
        for (int z = 0; z < 128; z++) s += vf[m*128+z] * T[z*384+j];
        g_G[idx] = s;
    } else if (idx < 3*128*384) {
        int rem = idx - 2*128*384;
        g_G[idx] = Wiou[rem];
    } else if (idx < 3*128*384 + 128) {
        int m = idx - 3*128*384;
        float s = 0.f;
#pragma unroll 8
        for (int j = 0; j < 128; j++) s += Qf[m*128+j] * Vf[j];
        g_qv[m] = s;
    }
}

// ---------------- K1c: px = x . qv ; copy x into g_Z cols [256,384) ----------------
__global__ void k1c(const float* __restrict__ x) {
    int idx = blockIdx.x * blockDim.x + threadIdx.x;   // NN*32
    if (idx >= NN*32) return;
    int n = idx >> 5;
    int j = (idx & 31) * 4;
    float4 v = *(const float4*)(x + (size_t)n*128 + j);
    *(float4*)(g_Z + (size_t)n*384 + 256 + j) = v;
    float p = v.x*g_qv[j] + v.y*g_qv[j+1] + v.z*g_qv[j+2] + v.w*g_qv[j+3];
#pragma unroll
    for (int m = 1; m < 32; m <<= 1) p += shflr(p, m);
    if ((idx & 31) == 0) g_px[n] = p;
}

// ---------------- K2A (mma.sync bf16, 3-term split): hk = h_mail@Kf + epilogue ----------------
// SMEM: Kh 32K | Kl 32K | Ah 16K | Al 16K | Vf 512B | p_buf 1K
#define K2A_AB   65536
#define K2A_VF   98304
#define K2A_PB   98816
#define K2A_SMEM (K2A_PB + 1024)
__global__ void __launch_bounds__(512, 1)
k2a(const float* __restrict__ hmail, const float* __restrict__ Kf,
    const float* __restrict__ Vf, const int* __restrict__ etype) {
    extern __shared__ char smc[];
    const unsigned smb = smem_u32(smc);
    float* Vfs = (float*)(smc + K2A_VF);
    float* pb  = (float*)(smc + K2A_PB);
    const int tid = threadIdx.x, wid = tid >> 5, lane = tid & 31;
    const int wrow = wid & 7, ch = wid >> 3;       // row stripe, col half
    const unsigned AB = smb + K2A_AB;

    // weight prep: K[n][k] = Kf[k][n]; bf16 hi/lo; row stride 256B, XOR swizzle
    for (int idx = tid; idx < 128*128; idx += 512) {
        int n = idx & 127, k = idx >> 7;
        float kf = Kf[k*128 + n];
        __nv_bfloat16 kh = __float2bfloat16_rn(kf);
        __nv_bfloat16 kl = __float2bfloat16_rn(kf - __bfloat162float(kh));
        unsigned off = (unsigned)(n*256 + ((2*k) ^ ((n & 7) << 4)));
        *(__nv_bfloat16*)(smc + 0*32768 + off) = kh;
        *(__nv_bfloat16*)(smc + 1*32768 + off) = kl;
    }
    if (tid < 128) Vfs[tid] = Vf[tid];
    __syncthreads();

    for (int tile = blockIdx.x; tile < NTILES; tile += gridDim.x) {
        const size_t rbase = (size_t)tile * 128;

        float acc[4][2][4];
#pragma unroll
        for (int g = 0; g < 4; g++)
#pragma unroll
            for (int s = 0; s < 2; s++)
#pragma unroll
                for (int q = 0; q < 4; q++) acc[g][s][q] = 0.f;

        for (int chunk = 0; chunk < 2; chunk++) {
            // convert A chunk [128 rows x 64 k] -> Ah/Al
            {
                const int row = tid >> 2, seg = tid & 3;
                const float* src = hmail + (rbase + row)*128 + chunk*64 + seg*16;
                const unsigned rsw = (unsigned)((row & 7) << 4);
#pragma unroll
                for (int i = 0; i < 4; i++) {
                    float4 v = ((const float4*)src)[i];
                    unsigned h0, l0, h1, l1;
                    split2(v.x, v.y, h0, l0);
                    split2(v.z, v.w, h1, l1);
                    int j = seg*16 + i*4;
                    unsigned bo = (unsigned)(row*128 + ((2*j) ^ rsw));
                    *(unsigned*)(smc + K2A_AB + bo)             = h0;
                    *(unsigned*)(smc + K2A_AB + bo + 4)         = h1;
                    *(unsigned*)(smc + K2A_AB + 16384 + bo)     = l0;
                    *(unsigned*)(smc + K2A_AB + 16384 + bo + 4) = l1;
                }
            }
            __syncthreads();
            // MMA: warp = rows wrow*16..+15, cols ch*64..+63
            {
                const int arow = wrow*16 + (lane & 7) + ((lane >> 3) & 1) * 8;
                const unsigned arsw = (unsigned)((arow & 7) << 4);
                const int bn_l = (lane & 7) + (lane >> 4) * 8;
                const int bkb_l = ((lane >> 3) & 1) * 16;
#pragma unroll
                for (int kk = 0; kk < 4; kk++) {
                    unsigned akb = (unsigned)(kk*32 + (lane >> 4) * 16);
                    unsigned aoff = (unsigned)(arow*128) + (akb ^ arsw);
                    unsigned ah[4], al[4];
                    ldsm4(ah, AB + aoff);
                    ldsm4(al, AB + 16384 + aoff);
                    const int bkb = chunk*128 + kk*32 + bkb_l;
#pragma unroll
                    for (int g = 0; g < 4; g++) {
                        int bn = ch*64 + g*16 + bn_l;
                        unsigned boff = (unsigned)(bn*256) +
                                        ((unsigned)bkb ^ ((unsigned)(bn & 7) << 4));
                        unsigned kh[4], kl[4];
                        ldsm4(kh, smb + 0*32768 + boff);
                        ldsm4(kl, smb + 1*32768 + boff);
#pragma unroll
                        for (int s = 0; s < 2; s++) {
                            mma16816(acc[g][s], ah, kh[s*2], kh[s*2+1]);
                            mma16816(acc[g][s], ah, kl[s*2], kl[s*2+1]);
                            mma16816(acc[g][s], al, kh[s*2], kh[s*2+1]);
                        }
                    }
                }
            }
            __syncthreads();
        }

        // ---- epilogue ----
        const int rlo = wrow*16 + (lane >> 2);     // local mail row (node0)
        const int rhi = rlo + 8;                   // node1
        const int node0 = tile*TN + wrow*2, node1 = node0 + 1;

        // partial dots with Vf over this warp's 32 cols
        float plo = 0.f, phi = 0.f;
#pragma unroll
        for (int g = 0; g < 4; g++)
#pragma unroll
            for (int s = 0; s < 2; s++) {
                int c = ch*64 + g*16 + s*8 + (lane & 3)*2;
                plo += acc[g][s][0]*Vfs[c] + acc[g][s][1]*Vfs[c+1];
                phi += acc[g][s][2]*Vfs[c] + acc[g][s][3]*Vfs[c+1];
            }
        plo += shflr(plo, 1); plo += shflr(plo, 2);
        phi += shflr(phi, 1); phi += shflr(phi, 2);
        if ((lane & 3) == 0) {
            pb[ch*128 + rlo] = plo;
            pb[ch*128 + rhi] = phi;
        }
        __syncthreads();
        float p_lo = pb[rlo] + pb[128 + rlo];
        float p_hi = pb[rhi] + pb[128 + rhi];

        float e_lo = (float)etype[rbase + rlo];
        float e_hi = (float)etype[rbase + rhi];
        float sc_lo = tanhf(g_px[node0] + p_lo);
        float sc_hi = tanhf(g_px[node1] + p_hi);

        float mx0 = sc_lo, mx1 = sc_hi, se0, se1, sm0 = e_lo, sm1 = e_hi;
#pragma unroll
        for (int m = 4; m < 32; m <<= 1) {
            mx0 = fmaxf(mx0, shflr(mx0, m));
            mx1 = fmaxf(mx1, shflr(mx1, m));
            sm0 += shflr(sm0, m);
            sm1 += shflr(sm1, m);
        }
        float ex0 = expf(sc_lo - mx0), ex1 = expf(sc_hi - mx1);
        se0 = ex0; se1 = ex1;
#pragma unroll
        for (int m = 4; m < 32; m <<= 1) { se0 += shflr(se0, m); se1 += shflr(se1, m); }
        float w0 = ex0 / se0, w1 = ex1 / se1;
        float mod0 = sm0 * 0.125f, mod1 = sm1 * 0.125f;
        float c1_lo = w0 * (1.f - mod0) * e_lo;        // -> sA
        float c0_lo = w0 * mod0 * (1.f - e_lo);        // -> sB
        float c1_hi = w1 * (1.f - mod1) * e_hi;
        float c0_hi = w1 * mod1 * (1.f - e_hi);

#pragma unroll
        for (int g = 0; g < 4; g++)
#pragma unroll
            for (int s = 0; s < 2; s++) {
                float b00 = c0_lo*acc[g][s][0], b01 = c0_lo*acc[g][s][1];
                float a00 = c1_lo*acc[g][s][0], a01 = c1_lo*acc[g][s][1];
                float b10 = c0_hi*acc[g][s][2], b11 = c0_hi*acc[g][s][3];
                float a10 = c1_hi*acc[g][s][2], a11 = c1_hi*acc[g][s][3];
#pragma unroll
                for (int m = 4; m < 32; m <<= 1) {
                    b00 += shflr(b00, m); b01 += shflr(b01, m);
                    a00 += shflr(a00, m); a01 += shflr(a01, m);
                    b10 += shflr(b10, m); b11 += shflr(b11, m);
                    a10 += shflr(a10, m); a11 += shflr(a11, m);
                }
                if (lane < 4) {
                    int c = ch*64 + g*16 + s*8 + lane*2;
                    float* Zr = g_Z + (size_t)node0 * 384;
                    *(float2*)(Zr + c)       = make_float2(b00, b01);
                    *(float2*)(Zr + 128 + c) = make_float2(a00, a01);
                } else if (lane < 8) {
                    int c = ch*64 + g*16 + s*8 + (lane - 4)*2;
                    float* Zr = g_Z + (size_t)node1 * 384;
                    *(float2*)(Zr + c)       = make_float2(b10, b11);
                    *(float2*)(Zr + 128 + c) = make_float2(a10, a11);
                }
            }
        __syncthreads();   // protect p_buf and A tiles before next tile
    }
}

// ---------------- K2B (mma.sync bf16, 3-term split, e-mask in registers) ----------------
// acc[row][j] = hm[row] @ Zf[:,j] + (e[row]*hm[row]) @ D[:,j],  D = Of - Zf
// SMEM: Zh,Zl,Dh,Dl 4x32K | Ah,Al 2x16K
#define K2B_AB   131072
#define K2B_SMEM (131072 + 32768)
__global__ void __launch_bounds__(512, 1)
k2b(const float* __restrict__ hmail, const float* __restrict__ cmail,
    const float* __restrict__ Of, const float* __restrict__ Zf,
    const int* __restrict__ etype) {
    extern __shared__ char smc[];
    const unsigned smb = smem_u32(smc);
    const int tid = threadIdx.x, wid = tid >> 5, lane = tid & 31;
    const int wrow = wid & 7, ch = wid >> 3;
    const unsigned AB = smb + K2B_AB;

    for (int idx = tid; idx < 128*128; idx += 512) {
        int n = idx & 127, k = idx >> 7;
        float zf = Zf[k*128 + n];
        float d  = Of[k*128 + n] - zf;
        __nv_bfloat16 zh = __float2bfloat16_rn(zf);
        __nv_bfloat16 zl = __float2bfloat16_rn(zf - __bfloat162float(zh));
        __nv_bfloat16 dh = __float2bfloat16_rn(d);
        __nv_bfloat16 dl = __float2bfloat16_rn(d - __bfloat162float(dh));
        unsigned off = (unsigned)(n*256 + ((2*k) ^ ((n & 7) << 4)));
        *(__nv_bfloat16*)(smc + 0*32768 + off) = zh;
        *(__nv_bfloat16*)(smc + 1*32768 + off) = zl;
        *(__nv_bfloat16*)(smc + 2*32768 + off) = dh;
        *(__nv_bfloat16*)(smc + 3*32768 + off) = dl;
    }
    __syncthreads();

    for (int tile = blockIdx.x; tile < NTILES; tile += gridDim.x) {
        const size_t rbase = (size_t)tile * 128;

        // per-thread A-fragment row masks (regs 0,2 -> rlo ; regs 1,3 -> rhi)
        const unsigned mlo = (etype[rbase + wrow*16 + (lane >> 2)]     != 0) ? 0xffffffffu : 0u;
        const unsigned mhi = (etype[rbase + wrow*16 + 8 + (lane >> 2)] != 0) ? 0xffffffffu : 0u;

        float acc[4][2][4];
#pragma unroll
        for (int g = 0; g < 4; g++)
#pragma unroll
            for (int s = 0; s < 2; s++)
#pragma unroll
                for (int q = 0; q < 4; q++) acc[g][s][q] = 0.f;

        for (int chunk = 0; chunk < 2; chunk++) {
            {
                const int row = tid >> 2, seg = tid & 3;
                const float* src = hmail + (rbase + row)*128 + chunk*64 + seg*16;
                const unsigned rsw = (unsigned)((row & 7) << 4);
#pragma unroll
                for (int i = 0; i < 4; i++) {
                    float4 v = ((const float4*)src)[i];
                    unsigned h0, l0, h1, l1;
                    split2(v.x, v.y, h0, l0);
                    split2(v.z, v.w, h1, l1);
                    int j = seg*16 + i*4;
                    unsigned bo = (unsigned)(row*128 + ((2*j) ^ rsw));
                    *(unsigned*)(smc + K2B_AB + bo)             = h0;
                    *(unsigned*)(smc + K2B_AB + bo + 4)         = h1;
                    *(unsigned*)(smc + K2B_AB + 16384 + bo)     = l0;
                    *(unsigned*)(smc + K2B_AB + 16384 + bo + 4) = l1;
                }
            }
            __syncthreads();
            {
                const int arow = wrow*16 + (lane & 7) + ((lane >> 3) & 1) * 8;
                const unsigned arsw = (unsigned)((arow & 7) << 4);
                const int bn_l = (lane & 7) + (lane >> 4) * 8;
                const int bkb_l = ((lane >> 3) & 1) * 16;
#pragma unroll
                for (int kk = 0; kk < 4; kk++) {
                    unsigned akb = (unsigned)(kk*32 + (lane >> 4) * 16);
                    unsigned aoff = (unsigned)(arow*128) + (akb ^ arsw);
                    unsigned ah[4], al[4], aeh[4], ael[4];
                    ldsm4(ah, AB + aoff);
                    ldsm4(al, AB + 16384 + aoff);
                    aeh[0] = ah[0] & mlo; aeh[1] = ah[1] & mhi;
                    aeh[2] = ah[2] & mlo; aeh[3] = ah[3] & mhi;
                    ael[0] = al[0] & mlo; ael[1] = al[1] & mhi;
                    ael[2] = al[2] & mlo; ael[3] = al[3] & mhi;
                    const int bkb = chunk*128 + kk*32 + bkb_l;
#pragma unroll
                    for (int g = 0; g < 4; g++) {
                        int bn = ch*64 + g*16 + bn_l;
                        unsigned boff = (unsigned)(bn*256) +
                                        ((unsigned)bkb ^ ((unsigned)(bn & 7) << 4));
                        unsigned zh[4], zl[4], dh[4], dl[4];
                        ldsm4(zh, smb + 0*32768 + boff);
                        ldsm4(zl, smb + 1*32768 + boff);
                        ldsm4(dh, smb + 2*32768 + boff);
                        ldsm4(dl, smb + 3*32768 + boff);
#pragma unroll
                        for (int s = 0; s < 2; s++) {
                            mma16816(acc[g][s], ah,  zh[s*2], zh[s*2+1]);
                            mma16816(acc[g][s], ah,  zl[s*2], zl[s*2+1]);
                            mma16816(acc[g][s], al,  zh[s*2], zh[s*2+1]);
                            mma16816(acc[g][s], aeh, dh[s*2], dh[s*2+1]);
                            mma16816(acc[g][s], aeh, dl[s*2], dl[s*2+1]);
                            mma16816(acc[g][s], ael, dh[s*2], dh[s*2+1]);
                        }
                    }
                }
            }
            __syncthreads();
        }

        // epilogue: f = sigmoid(acc); c_red = sum over 8 mail rows of f*c_mail
        {
            const int rlo = wrow*16 + (lane >> 2);
            const int rhi = rlo + 8;
            const int node0 = tile*TN + wrow*2;
#pragma unroll
            for (int g = 0; g < 4; g++)
#pragma unroll
                for (int s = 0; s < 2; s++) {
                    int col = ch*64 + g*16 + s*8 + (lane & 3)*2;
                    float2 c0 = *(const float2*)(cmail + (rbase + rlo)*128 + col);
                    float2 c1 = *(const float2*)(cmail + (rbase + rhi)*128 + col);
                    float v0 = c0.x / (1.f + expf(-acc[g][s][0]));
                    float v1 = c0.y / (1.f + expf(-acc[g][s][1]));
                    float v2 = c1.x / (1.f + expf(-acc[g][s][2]));
                    float v3 = c1.y / (1.f + expf(-acc[g][s][3]));
#pragma unroll
                    for (int m = 4; m < 32; m <<= 1) {
                        v0 += shflr(v0, m); v1 += shflr(v1, m);
                        v2 += shflr(v2, m); v3 += shflr(v3, m);
                    }
                    if (lane < 4) {
                        int c = ch*64 + g*16 + s*8 + lane*2;
                        *(float2*)(g_cred + (size_t)node0*128 + c) = make_float2(v0, v1);
                    } else if (lane < 8) {
                        int c = ch*64 + g*16 + s*8 + (lane - 4)*2;
                        *(float2*)(g_cred + (size_t)(node0+1)*128 + c) = make_float2(v2, v3);
                    }
                }
        }
    }
}

// ---------------- K3a: IOU = Z @ G + biou ----------------
__global__ void __launch_bounds__(256, 2)
k3a(const float* __restrict__ biou) {
    __shared__ float As[32*132];
    __shared__ float Bs[32*128];
    const int tid = threadIdx.x, tx = tid & 15, ty = tid >> 4;
    const int bx = blockIdx.x;
    const int by = blockIdx.y;
    const float* A = g_Z + (size_t)by * 128 * 384;

    float acc[8][8];
#pragma unroll
    for (int a = 0; a < 8; a++)
#pragma unroll
        for (int b = 0; b < 8; b++) acc[a][b] = 0.f;

    for (int kb = 0; kb < 384; kb += 32) {
        __syncthreads();
        {
            int cg = tid & 7, r0 = tid >> 3;
#pragma unroll
            for (int p = 0; p < 4; p++) {
                int r = r0 + p*32;
                float4 v = *(const float4*)(A + (size_t)r*384 + kb + cg*4);
                As[(cg*4+0)*132 + r] = v.x;
                As[(cg*4+1)*132 + r] = v.y;
                As[(cg*4+2)*132 + r] = v.z;
                As[(cg*4+3)*132 + r] = v.w;
            }
        }
        {
#pragma unroll
            for (int it = 0; it < 4; it++) {
                int flat = it*256 + tid;
                int kk = flat >> 5, j4 = flat & 31;
                *(float4*)(Bs + kk*128 + j4*4) =
                    *(const float4*)(g_G + (size_t)(kb+kk)*384 + bx*128 + j4*4);
            }
        }
        __syncthreads();
#pragma unroll 8
        for (int kk = 0; kk < 32; kk++) {
            float4 a0 = *(const float4*)(As + kk*132 + ty*8);
            float4 a1 = *(const float4*)(As + kk*132 + ty*8 + 4);
            float4 b0 = *(const float4*)(Bs + kk*128 + tx*4);
            float4 b1 = *(const float4*)(Bs + kk*128 + 64 + tx*4);
            float a[8] = {a0.x,a0.y,a0.z,a0.w,a1.x,a1.y,a1.z,a1.w};
            float b[8] = {b0.x,b0.y,b0.z,b0.w,b1.x,b1.y,b1.z,b1.w};
#pragma unroll
            for (int rr = 0; rr < 8; rr++)
#pragma unroll
                for (int cc = 0; cc < 8; cc++)
                    acc[rr][cc] += a[rr]*b[cc];
        }
    }
    int jb = bx*128;
    float bi0[4], bi1[4];
#pragma unroll
    for (int q = 0; q < 4; q++) {
        bi0[q] = biou[jb + tx*4 + q];
        bi1[q] = biou[jb + 64 + tx*4 + q];
    }
#pragma unroll
    for (int rr = 0; rr < 8; rr++) {
        size_t row = (size_t)by*128 + ty*8 + rr;
        float* op = g_IOU + row*384 + jb;
        *(float4*)(op + tx*4) = make_float4(acc[rr][0]+bi0[0], acc[rr][1]+bi0[1],
                                            acc[rr][2]+bi0[2], acc[rr][3]+bi0[3]);
        *(float4*)(op + 64 + tx*4) = make_float4(acc[rr][4]+bi1[0], acc[rr][5]+bi1[1],
                                                 acc[rr][6]+bi1[2], acc[rr][7]+bi1[3]);
    }
}

// ---------------- K3b: gates -> out ----------------
__global__ void k3b(float* __restrict__ out) {
    int idx = blockIdx.x * blockDim.x + threadIdx.x;
    if (idx >= NN*32) return;
    int n = idx >> 5;
    int j = (idx & 31) * 4;
    const float* r = g_IOU + (size_t)n * 384;
    float4 iv = *(const float4*)(r + j);
    float4 ov = *(const float4*)(r + 128 + j);
    float4 uv = *(const float4*)(r + 256 + j);
    float4 cr = *(const float4*)(g_cred + (size_t)n*128 + j);
    float4 hc, cc;
    {
        float ig, og, ug, c, h;
        ig = 1.f/(1.f+expf(-iv.x)); og = 1.f/(1.f+expf(-ov.x)); ug = tanhf(uv.x);
        c = ig*ug + cr.x; h = og*tanhf(c); hc.x = h; cc.x = c;
        ig = 1.f/(1.f+expf(-iv.y)); og = 1.f/(1.f+expf(-ov.y)); ug = tanhf(uv.y);
        c = ig*ug + cr.y; h = og*tanhf(c); hc.y = h; cc.y = c;
        ig = 1.f/(1.f+expf(-iv.z)); og = 1.f/(1.f+expf(-ov.z)); ug = tanhf(uv.z);
        c = ig*ug + cr.z; h = og*tanhf(c); hc.z = h; cc.z = c;
        ig = 1.f/(1.f+expf(-iv.w)); og = 1.f/(1.f+expf(-ov.w)); ug = tanhf(uv.w);
        c = ig*ug + cr.w; h = og*tanhf(c); hc.w = h; cc.w = c;
    }
    *(float4*)(out + (size_t)n*128 + j) = hc;
    *(float4*)(out + (size_t)NN*128 + (size_t)n*128 + j) = cc;
}

// ---------------- launcher ----------------
extern "C" void kernel_launch(void* const* d_in, const int* in_sizes, int n_in,
                              void* d_out, int out_size) {
    const float* x      = (const float*)d_in[0];
    const float* h_mail = (const float*)d_in[1];
    const float* c_mail = (const float*)d_in[2];
    const float* Wiou   = (const float*)d_in[3];
    const float* Uiou   = (const float*)d_in[4];
    const float* biou   = (const float*)d_in[5];
    const float* Of     = (const float*)d_in[6];
    const float* Zf     = (const float*)d_in[7];
    const float* Qf     = (const float*)d_in[8];
    const float* Kf     = (const float*)d_in[9];
    const float* vf     = (const float*)d_in[10];
    const float* Wa     = (const float*)d_in[11];
    const float* Wd     = (const float*)d_in[12];
    const float* Vf     = (const float*)d_in[13];
    const int*   etype  = (const int*)d_in[14];
    float* out = (float*)d_out;

    cudaFuncSetAttribute(k2a, cudaFuncAttributeMaxDynamicSharedMemorySize, K2A_SMEM);
    cudaFuncSetAttribute(k2b, cudaFuncAttributeMaxDynamicSharedMemorySize, K2B_SMEM);

    k1a<<<384, 256>>>(Wa, Wd, Uiou);
    k1b<<<577, 256>>>(vf, Wiou, Qf, Vf);
    k1c<<<6250, 256>>>(x);
    k2a<<<148, 512, K2A_SMEM>>>(h_mail, Kf, Vf, etype);
    k2b<<<148, 512, K2B_SMEM>>>(h_mail, c_mail, Of, Zf, etype);
    k3a<<<dim3(3, 391), 256>>>(biou);
    k3b<<<6250, 256>>>(out);
}

// round 9
// speedup vs baseline: 1.7617x; 1.0691x over previous
#include <cuda_runtime.h>
#include <cuda_bf16.h>
#include <math.h>

#define NN 50000
#define HH 128
#define NPAD 50048            // 391*128, padded rows (zero-init)
#define TN 16                 // nodes per tile (16*8 = 128 rows)
#define NTILES (NN/TN)        // 3125

// ---------------- scratch (__device__ globals; zero-initialized) ----------------
__device__ float g_T[2*128*384];              // Wd@U0 | Wa@U1
__device__ float g_G[384*384];                // [vf@Wd@U0 ; vf@Wa@U1 ; Wiou]
__device__ float g_qv[128];                   // Qf @ Vf
__device__ float g_px[NN];                    // x . qv  (per node)
__device__ __nv_bfloat16 g_Zh[(size_t)NPAD*384];  // Z hi (bf16 split)
__device__ __nv_bfloat16 g_Zl[(size_t)NPAD*384];  // Z lo
__device__ float g_IOU[(size_t)NPAD*384];
__device__ float g_cred[(size_t)NN*128];

// ================= helpers =================
__device__ __forceinline__ unsigned smem_u32(const void* p) {
    unsigned a;
    asm("{ .reg .u64 t; cvta.to.shared.u64 t, %1; cvt.u32.u64 %0, t; }" : "=r"(a) : "l"(p));
    return a;
}

__device__ __forceinline__ void ldsm4(unsigned r[4], unsigned addr) {
    asm volatile("ldmatrix.sync.aligned.m8n8.x4.shared.b16 {%0,%1,%2,%3}, [%4];"
                 : "=r"(r[0]), "=r"(r[1]), "=r"(r[2]), "=r"(r[3]) : "r"(addr));
}

__device__ __forceinline__ void mma16816(float c[4], const unsigned a[4],
                                         unsigned b0, unsigned b1) {
    asm volatile("mma.sync.aligned.m16n8k16.row.col.f32.bf16.bf16.f32 "
                 "{%0,%1,%2,%3}, {%4,%5,%6,%7}, {%8,%9}, {%0,%1,%2,%3};"
                 : "+f"(c[0]), "+f"(c[1]), "+f"(c[2]), "+f"(c[3])
                 : "r"(a[0]), "r"(a[1]), "r"(a[2]), "r"(a[3]), "r"(b0), "r"(b1));
}

// fp32 -> bf16 hi/lo split, 2 elements packed per word
__device__ __forceinline__ void split2(float a, float b, unsigned& hi, unsigned& lo) {
    __nv_bfloat16 ha = __float2bfloat16_rn(a);
    __nv_bfloat16 hb = __float2bfloat16_rn(b);
    __nv_bfloat16 la = __float2bfloat16_rn(a - __bfloat162float(ha));
    __nv_bfloat16 lb = __float2bfloat16_rn(b - __bfloat162float(hb));
    hi = ((unsigned)__bfloat16_as_ushort(hb) << 16) | (unsigned)__bfloat16_as_ushort(ha);
    lo = ((unsigned)__bfloat16_as_ushort(lb) << 16) | (unsigned)__bfloat16_as_ushort(la);
}

__device__ __forceinline__ float shflr(float v, int m) {
    return __shfl_xor_sync(0xffffffffu, v, m);
}

// ---------------- K1a: T0 = Wd@U0, T1 = Wa@U1 ----------------
__global__ void k1a(const float* __restrict__ Wa, const float* __restrict__ Wd,
                    const float* __restrict__ Uiou) {
    int idx = blockIdx.x * blockDim.x + threadIdx.x;
    if (idx >= 2*128*384) return;
    int which = idx / (128*384);
    int rem   = idx - which*(128*384);
    int m = rem / 384, j = rem - m*384;
    const float* W = which ? Wa : Wd;
    const float* U = Uiou + which*(128*384);
    float s = 0.f;
#pragma unroll 8
    for (int z = 0; z < 128; z++) s += W[m*128+z] * U[z*384+j];
    g_T[idx] = s;
}

// ---------------- K1b: G rows; qv = Qf@Vf ----------------
__global__ void k1b(const float* __restrict__ vf, const float* __restrict__ Wiou,
                    const float* __restrict__ Qf, const float* __restrict__ Vf) {
    int idx = blockIdx.x * blockDim.x + threadIdx.x;
    if (idx < 2*128*384) {
        int which = idx / (128*384);
        int rem   = idx - which*(128*384);
        int m = rem / 384, j = rem - m*384;
        const float* T = g_T + which*(128*384);
        float s = 0.f;
#pragma unroll 8
        for (int z = 0; z < 128; z++) s += vf[m*128+z] * T[z*384+j];
        g_G[idx] = s;
    } else if (idx < 3*128*384) {
        int rem = idx - 2*128*384;
        g_G[idx] = Wiou[rem];
    } else if (idx < 3*128*384 + 128) {
        int m = idx - 3*128*384;
        float s = 0.f;
#pragma unroll 8
        for (int j = 0; j < 128; j++) s += Qf[m*128+j] * Vf[j];
        g_qv[m] = s;
    }
}

// ---------------- K1c: px = x . qv ; x -> Zh/Zl cols [256,384) ----------------
__global__ void k1c(const float* __restrict__ x) {
    int idx = blockIdx.x * blockDim.x + threadIdx.x;   // NN*32
    if (idx >= NN*32) return;
    int n = idx >> 5;
    int j = (idx & 31) * 4;
    float4 v = *(const float4*)(x + (size_t)n*128 + j);
    unsigned h0, l0, h1, l1;
    split2(v.x, v.y, h0, l0);
    split2(v.z, v.w, h1, l1);
    size_t o = (size_t)n*384 + 256 + j;
    *(unsigned*)(g_Zh + o)     = h0;
    *(unsigned*)(g_Zh + o + 2) = h1;
    *(unsigned*)(g_Zl + o)     = l0;
    *(unsigned*)(g_Zl + o + 2) = l1;
    float p = v.x*g_qv[j] + v.y*g_qv[j+1] + v.z*g_qv[j+2] + v.w*g_qv[j+3];
#pragma unroll
    for (int m = 1; m < 32; m <<= 1) p += shflr(p, m);
    if ((idx & 31) == 0) g_px[n] = p;
}

// ---------------- K2A (mma.sync bf16, 3-term split): hk = h_mail@Kf + epilogue ----------------
// SMEM: Kh 32K | Kl 32K | Ah 16K | Al 16K | Vf 512B | p_buf 1K
#define K2A_AB   65536
#define K2A_VF   98304
#define K2A_PB   98816
#define K2A_SMEM (K2A_PB + 1024)
__global__ void __launch_bounds__(512, 1)
k2a(const float* __restrict__ hmail, const float* __restrict__ Kf,
    const float* __restrict__ Vf, const int* __restrict__ etype) {
    extern __shared__ char smc[];
    const unsigned smb = smem_u32(smc);
    float* Vfs = (float*)(smc + K2A_VF);
    float* pb  = (float*)(smc + K2A_PB);
    const int tid = threadIdx.x, wid = tid >> 5, lane = tid & 31;
    const int wrow = wid & 7, ch = wid >> 3;       // row stripe, col half
    const unsigned AB = smb + K2A_AB;

    // weight prep: K[n][k] = Kf[k][n]; bf16 hi/lo; row stride 256B, XOR swizzle
    for (int idx = tid; idx < 128*128; idx += 512) {
        int n = idx & 127, k = idx >> 7;
        float kf = Kf[k*128 + n];
        __nv_bfloat16 kh = __float2bfloat16_rn(kf);
        __nv_bfloat16 kl = __float2bfloat16_rn(kf - __bfloat162float(kh));
        unsigned off = (unsigned)(n*256 + ((2*k) ^ ((n & 7) << 4)));
        *(__nv_bfloat16*)(smc + 0*32768 + off) = kh;
        *(__nv_bfloat16*)(smc + 1*32768 + off) = kl;
    }
    if (tid < 128) Vfs[tid] = Vf[tid];
    __syncthreads();

    for (int tile = blockIdx.x; tile < NTILES; tile += gridDim.x) {
        const size_t rbase = (size_t)tile * 128;

        float acc[4][2][4];
#pragma unroll
        for (int g = 0; g < 4; g++)
#pragma unroll
            for (int s = 0; s < 2; s++)
#pragma unroll
                for (int q = 0; q < 4; q++) acc[g][s][q] = 0.f;

        for (int chunk = 0; chunk < 2; chunk++) {
            // convert A chunk [128 rows x 64 k] -> Ah/Al
            {
                const int row = tid >> 2, seg = tid & 3;
                const float* src = hmail + (rbase + row)*128 + chunk*64 + seg*16;
                const unsigned rsw = (unsigned)((row & 7) << 4);
#pragma unroll
                for (int i = 0; i < 4; i++) {
                    float4 v = ((const float4*)src)[i];
                    unsigned h0, l0, h1, l1;
                    split2(v.x, v.y, h0, l0);
                    split2(v.z, v.w, h1, l1);
                    int j = seg*16 + i*4;
                    unsigned bo = (unsigned)(row*128 + ((2*j) ^ rsw));
                    *(unsigned*)(smc + K2A_AB + bo)             = h0;
                    *(unsigned*)(smc + K2A_AB + bo + 4)         = h1;
                    *(unsigned*)(smc + K2A_AB + 16384 + bo)     = l0;
                    *(unsigned*)(smc + K2A_AB + 16384 + bo + 4) = l1;
                }
            }
            __syncthreads();
            // MMA: warp = rows wrow*16..+15, cols ch*64..+63
            {
                const int arow = wrow*16 + (lane & 7) + ((lane >> 3) & 1) * 8;
                const unsigned arsw = (unsigned)((arow & 7) << 4);
                const int bn_l = (lane & 7) + (lane >> 4) * 8;
                const int bkb_l = ((lane >> 3) & 1) * 16;
#pragma unroll
                for (int kk = 0; kk < 4; kk++) {
                    unsigned akb = (unsigned)(kk*32 + (lane >> 4) * 16);
                    unsigned aoff = (unsigned)(arow*128) + (akb ^ arsw);
                    unsigned ah[4], al[4];
                    ldsm4(ah, AB + aoff);
                    ldsm4(al, AB + 16384 + aoff);
                    const int bkb = chunk*128 + kk*32 + bkb_l;
#pragma unroll
                    for (int g = 0; g < 4; g++) {
                        int bn = ch*64 + g*16 + bn_l;
                        unsigned boff = (unsigned)(bn*256) +
                                        ((unsigned)bkb ^ ((unsigned)(bn & 7) << 4));
                        unsigned kh[4], kl[4];
                        ldsm4(kh, smb + 0*32768 + boff);
                        ldsm4(kl, smb + 1*32768 + boff);
#pragma unroll
                        for (int s = 0; s < 2; s++) {
                            mma16816(acc[g][s], ah, kh[s*2], kh[s*2+1]);
                            mma16816(acc[g][s], ah, kl[s*2], kl[s*2+1]);
                            mma16816(acc[g][s], al, kh[s*2], kh[s*2+1]);
                        }
                    }
                }
            }
            __syncthreads();
        }

        // ---- epilogue ----
        const int rlo = wrow*16 + (lane >> 2);     // local mail row (node0)
        const int rhi = rlo + 8;                   // node1
        const int node0 = tile*TN + wrow*2, node1 = node0 + 1;

        float plo = 0.f, phi = 0.f;
#pragma unroll
        for (int g = 0; g < 4; g++)
#pragma unroll
            for (int s = 0; s < 2; s++) {
                int c = ch*64 + g*16 + s*8 + (lane & 3)*2;
                plo += acc[g][s][0]*Vfs[c] + acc[g][s][1]*Vfs[c+1];
                phi += acc[g][s][2]*Vfs[c] + acc[g][s][3]*Vfs[c+1];
            }
        plo += shflr(plo, 1); plo += shflr(plo, 2);
        phi += shflr(phi, 1); phi += shflr(phi, 2);
        if ((lane & 3) == 0) {
            pb[ch*128 + rlo] = plo;
            pb[ch*128 + rhi] = phi;
        }
        __syncthreads();
        float p_lo = pb[rlo] + pb[128 + rlo];
        float p_hi = pb[rhi] + pb[128 + rhi];

        float e_lo = (float)etype[rbase + rlo];
        float e_hi = (float)etype[rbase + rhi];
        float sc_lo = tanhf(g_px[node0] + p_lo);
        float sc_hi = tanhf(g_px[node1] + p_hi);

        float mx0 = sc_lo, mx1 = sc_hi, se0, se1, sm0 = e_lo, sm1 = e_hi;
#pragma unroll
        for (int m = 4; m < 32; m <<= 1) {
            mx0 = fmaxf(mx0, shflr(mx0, m));
            mx1 = fmaxf(mx1, shflr(mx1, m));
            sm0 += shflr(sm0, m);
            sm1 += shflr(sm1, m);
        }
        float ex0 = expf(sc_lo - mx0), ex1 = expf(sc_hi - mx1);
        se0 = ex0; se1 = ex1;
#pragma unroll
        for (int m = 4; m < 32; m <<= 1) { se0 += shflr(se0, m); se1 += shflr(se1, m); }
        float w0 = ex0 / se0, w1 = ex1 / se1;
        float mod0 = sm0 * 0.125f, mod1 = sm1 * 0.125f;
        float c1_lo = w0 * (1.f - mod0) * e_lo;
        float c0_lo = w0 * mod0 * (1.f - e_lo);
        float c1_hi = w1 * (1.f - mod1) * e_hi;
        float c0_hi = w1 * mod1 * (1.f - e_hi);

#pragma unroll
        for (int g = 0; g < 4; g++)
#pragma unroll
            for (int s = 0; s < 2; s++) {
                float b00 = c0_lo*acc[g][s][0], b01 = c0_lo*acc[g][s][1];
                float a00 = c1_lo*acc[g][s][0], a01 = c1_lo*acc[g][s][1];
                float b10 = c0_hi*acc[g][s][2], b11 = c0_hi*acc[g][s][3];
                float a10 = c1_hi*acc[g][s][2], a11 = c1_hi*acc[g][s][3];
#pragma unroll
                for (int m = 4; m < 32; m <<= 1) {
                    b00 += shflr(b00, m); b01 += shflr(b01, m);
                    a00 += shflr(a00, m); a01 += shflr(a01, m);
                    b10 += shflr(b10, m); b11 += shflr(b11, m);
                    a10 += shflr(a10, m); a11 += shflr(a11, m);
                }
                if (lane < 4) {
                    int c = ch*64 + g*16 + s*8 + lane*2;
                    size_t ro = (size_t)node0 * 384;
                    unsigned hi, lo;
                    split2(b00, b01, hi, lo);
                    *(unsigned*)(g_Zh + ro + c) = hi;
                    *(unsigned*)(g_Zl + ro + c) = lo;
                    split2(a00, a01, hi, lo);
                    *(unsigned*)(g_Zh + ro + 128 + c) = hi;
                    *(unsigned*)(g_Zl + ro + 128 + c) = lo;
                } else if (lane < 8) {
                    int c = ch*64 + g*16 + s*8 + (lane - 4)*2;
                    size_t ro = (size_t)node1 * 384;
                    unsigned hi, lo;
                    split2(b10, b11, hi, lo);
                    *(unsigned*)(g_Zh + ro + c) = hi;
                    *(unsigned*)(g_Zl + ro + c) = lo;
                    split2(a10, a11, hi, lo);
                    *(unsigned*)(g_Zh + ro + 128 + c) = hi;
                    *(unsigned*)(g_Zl + ro + 128 + c) = lo;
                }
            }
        __syncthreads();   // protect p_buf and A tiles before next tile
    }
}

// ---------------- K2B (mma.sync bf16, 3-term split, e-mask in registers) ----------------
#define K2B_AB   131072
#define K2B_SMEM (131072 + 32768)
__global__ void __launch_bounds__(512, 1)
k2b(const float* __restrict__ hmail, const float* __restrict__ cmail,
    const float* __restrict__ Of, const float* __restrict__ Zf,
    const int* __restrict__ etype) {
    extern __shared__ char smc[];
    const unsigned smb = smem_u32(smc);
    const int tid = threadIdx.x, wid = tid >> 5, lane = tid & 31;
    const int wrow = wid & 7, ch = wid >> 3;
    const unsigned AB = smb + K2B_AB;

    for (int idx = tid; idx < 128*128; idx += 512) {
        int n = idx & 127, k = idx >> 7;
        float zf = Zf[k*128 + n];
        float d  = Of[k*128 + n] - zf;
        __nv_bfloat16 zh = __float2bfloat16_rn(zf);
        __nv_bfloat16 zl = __float2bfloat16_rn(zf - __bfloat162float(zh));
        __nv_bfloat16 dh = __float2bfloat16_rn(d);
        __nv_bfloat16 dl = __float2bfloat16_rn(d - __bfloat162float(dh));
        unsigned off = (unsigned)(n*256 + ((2*k) ^ ((n & 7) << 4)));
        *(__nv_bfloat16*)(smc + 0*32768 + off) = zh;
        *(__nv_bfloat16*)(smc + 1*32768 + off) = zl;
        *(__nv_bfloat16*)(smc + 2*32768 + off) = dh;
        *(__nv_bfloat16*)(smc + 3*32768 + off) = dl;
    }
    __syncthreads();

    for (int tile = blockIdx.x; tile < NTILES; tile += gridDim.x) {
        const size_t rbase = (size_t)tile * 128;

        const unsigned mlo = (etype[rbase + wrow*16 + (lane >> 2)]     != 0) ? 0xffffffffu : 0u;
        const unsigned mhi = (etype[rbase + wrow*16 + 8 + (lane >> 2)] != 0) ? 0xffffffffu : 0u;

        float acc[4][2][4];
#pragma unroll
        for (int g = 0; g < 4; g++)
#pragma unroll
            for (int s = 0; s < 2; s++)
#pragma unroll
                for (int q = 0; q < 4; q++) acc[g][s][q] = 0.f;

        for (int chunk = 0; chunk < 2; chunk++) {
            {
                const int row = tid >> 2, seg = tid & 3;
                const float* src = hmail + (rbase + row)*128 + chunk*64 + seg*16;
                const unsigned rsw = (unsigned)((row & 7) << 4);
#pragma unroll
                for (int i = 0; i < 4; i++) {
                    float4 v = ((const float4*)src)[i];
                    unsigned h0, l0, h1, l1;
                    split2(v.x, v.y, h0, l0);
                    split2(v.z, v.w, h1, l1);
                    int j = seg*16 + i*4;
                    unsigned bo = (unsigned)(row*128 + ((2*j) ^ rsw));
                    *(unsigned*)(smc + K2B_AB + bo)             = h0;
                    *(unsigned*)(smc + K2B_AB + bo + 4)         = h1;
                    *(unsigned*)(smc + K2B_AB + 16384 + bo)     = l0;
                    *(unsigned*)(smc + K2B_AB + 16384 + bo + 4) = l1;
                }
            }
            __syncthreads();
            {
                const int arow = wrow*16 + (lane & 7) + ((lane >> 3) & 1) * 8;
                const unsigned arsw = (unsigned)((arow & 7) << 4);
                const int bn_l = (lane & 7) + (lane >> 4) * 8;
                const int bkb_l = ((lane >> 3) & 1) * 16;
#pragma unroll
                for (int kk = 0; kk < 4; kk++) {
                    unsigned akb = (unsigned)(kk*32 + (lane >> 4) * 16);
                    unsigned aoff = (unsigned)(arow*128) + (akb ^ arsw);
                    unsigned ah[4], al[4], aeh[4], ael[4];
                    ldsm4(ah, AB + aoff);
                    ldsm4(al, AB + 16384 + aoff);
                    aeh[0] = ah[0] & mlo; aeh[1] = ah[1] & mhi;
                    aeh[2] = ah[2] & mlo; aeh[3] = ah[3] & mhi;
                    ael[0] = al[0] & mlo; ael[1] = al[1] & mhi;
                    ael[2] = al[2] & mlo; ael[3] = al[3] & mhi;
                    const int bkb = chunk*128 + kk*32 + bkb_l;
#pragma unroll
                    for (int g = 0; g < 4; g++) {
                        int bn = ch*64 + g*16 + bn_l;
                        unsigned boff = (unsigned)(bn*256) +
                                        ((unsigned)bkb ^ ((unsigned)(bn & 7) << 4));
                        unsigned zh[4], zl[4], dh[4], dl[4];
                        ldsm4(zh, smb + 0*32768 + boff);
                        ldsm4(zl, smb + 1*32768 + boff);
                        ldsm4(dh, smb + 2*32768 + boff);
                        ldsm4(dl, smb + 3*32768 + boff);
#pragma unroll
                        for (int s = 0; s < 2; s++) {
                            mma16816(acc[g][s], ah,  zh[s*2], zh[s*2+1]);
                            mma16816(acc[g][s], ah,  zl[s*2], zl[s*2+1]);
                            mma16816(acc[g][s], al,  zh[s*2], zh[s*2+1]);
                            mma16816(acc[g][s], aeh, dh[s*2], dh[s*2+1]);
                            mma16816(acc[g][s], aeh, dl[s*2], dl[s*2+1]);
                            mma16816(acc[g][s], ael, dh[s*2], dh[s*2+1]);
                        }
                    }
                }
            }
            __syncthreads();
        }

        {
            const int rlo = wrow*16 + (lane >> 2);
            const int rhi = rlo + 8;
            const int node0 = tile*TN + wrow*2;
#pragma unroll
            for (int g = 0; g < 4; g++)
#pragma unroll
                for (int s = 0; s < 2; s++) {
                    int col = ch*64 + g*16 + s*8 + (lane & 3)*2;
                    float2 c0 = *(const float2*)(cmail + (rbase + rlo)*128 + col);
                    float2 c1 = *(const float2*)(cmail + (rbase + rhi)*128 + col);
                    float v0 = c0.x / (1.f + expf(-acc[g][s][0]));
                    float v1 = c0.y / (1.f + expf(-acc[g][s][1]));
                    float v2 = c1.x / (1.f + expf(-acc[g][s][2]));
                    float v3 = c1.y / (1.f + expf(-acc[g][s][3]));
#pragma unroll
                    for (int m = 4; m < 32; m <<= 1) {
                        v0 += shflr(v0, m); v1 += shflr(v1, m);
                        v2 += shflr(v2, m); v3 += shflr(v3, m);
                    }
                    if (lane < 4) {
                        int c = ch*64 + g*16 + s*8 + lane*2;
                        *(float2*)(g_cred + (size_t)node0*128 + c) = make_float2(v0, v1);
                    } else if (lane < 8) {
                        int c = ch*64 + g*16 + s*8 + (lane - 4)*2;
                        *(float2*)(g_cred + (size_t)(node0+1)*128 + c) = make_float2(v2, v3);
                    }
                }
        }
    }
}

// ---------------- K3a (mma.sync bf16, 3-term split): IOU = Z @ G + biou ----------------
// SMEM: Bh 96K | Bl 96K | Ah 16K | Al 16K  = 229376 B
#define K3_BL   98304
#define K3_AB   196608
#define K3_SMEM (196608 + 32768)
__global__ void __launch_bounds__(512, 1)
k3a(const float* __restrict__ biou) {
    extern __shared__ char smc[];
    const unsigned smb = smem_u32(smc);
    const int tid = threadIdx.x, wid = tid >> 5, lane = tid & 31;
    const int wrow = wid & 7, ch = wid >> 3;
    const int jb = blockIdx.x * 128;           // output col block
    const unsigned AB = smb + K3_AB;

    // B fill: B[n][k] = G[k][jb+n], bf16 hi/lo, row stride 768B, XOR swizzle
    for (int idx = tid; idx < 128*384; idx += 512) {
        int k = idx % 384, n = idx / 384;      // consecutive tid -> consecutive k (coalesced STS)
        float v = g_G[k*384 + jb + n];
        __nv_bfloat16 bh = __float2bfloat16_rn(v);
        __nv_bfloat16 bl = __float2bfloat16_rn(v - __bfloat162float(bh));
        unsigned off = (unsigned)(n*768 + ((2*k) ^ ((n & 7) << 4)));
        *(__nv_bfloat16*)(smc + off)          = bh;
        *(__nv_bfloat16*)(smc + K3_BL + off)  = bl;
    }
    __syncthreads();

    for (int rt = blockIdx.y; rt < 391; rt += gridDim.y) {
        const size_t rbase = (size_t)rt * 128;

        float acc[4][2][4];
#pragma unroll
        for (int g = 0; g < 4; g++)
#pragma unroll
            for (int s = 0; s < 2; s++)
#pragma unroll
                for (int q = 0; q < 4; q++) acc[g][s][q] = 0.f;

        for (int chunk = 0; chunk < 6; chunk++) {
            // A fill: copy [128 rows x 64 k] of Zh/Zl into swizzled SMEM
            {
                const int row = tid >> 2, seg = tid & 3;    // seg covers 16 k
                const size_t go = (rbase + row)*384 + chunk*64 + seg*16;
                const unsigned rsw = (unsigned)((row & 7) << 4);
#pragma unroll
                for (int i = 0; i < 2; i++) {               // 2 x 8 bf16
                    uint4 h = *(const uint4*)(g_Zh + go + i*8);
                    uint4 l = *(const uint4*)(g_Zl + go + i*8);
                    int j = seg*16 + i*8;
                    unsigned bo = (unsigned)(row*128 + ((2*j) ^ rsw));
                    *(uint4*)(smc + K3_AB + bo)         = h;
                    *(uint4*)(smc + K3_AB + 16384 + bo) = l;
                }
            }
            __syncthreads();
            {
                const int arow = wrow*16 + (lane & 7) + ((lane >> 3) & 1) * 8;
                const unsigned arsw = (unsigned)((arow & 7) << 4);
                const int bn_l = (lane & 7) + (lane >> 4) * 8;
                const int bkb_l = ((lane >> 3) & 1) * 16;
#pragma unroll
                for (int kk = 0; kk < 4; kk++) {
                    unsigned akb = (unsigned)(kk*32 + (lane >> 4) * 16);
                    unsigned aoff = (unsigned)(arow*128) + (akb ^ arsw);
                    unsigned ah[4], al[4];
                    ldsm4(ah, AB + aoff);
                    ldsm4(al, AB + 16384 + aoff);
                    const int bkb = chunk*128 + kk*32 + bkb_l;
#pragma unroll
                    for (int g = 0; g < 4; g++) {
                        int bn = ch*64 + g*16 + bn_l;
                        unsigned boff = (unsigned)(bn*768) +
                                        ((unsigned)bkb ^ ((unsigned)(bn & 7) << 4));
                        unsigned bh[4], bl[4];
                        ldsm4(bh, smb + boff);
                        ldsm4(bl, smb + K3_BL + boff);
#pragma unroll
                        for (int s = 0; s < 2; s++) {
                            mma16816(acc[g][s], ah, bh[s*2], bh[s*2+1]);
                            mma16816(acc[g][s], ah, bl[s*2], bl[s*2+1]);
                            mma16816(acc[g][s], al, bh[s*2], bh[s*2+1]);
                        }
                    }
                }
            }
            __syncthreads();
        }

        // epilogue: IOU = acc + biou
        {
            const size_t rlo = rbase + wrow*16 + (lane >> 2);
            const size_t rhi = rlo + 8;
#pragma unroll
            for (int g = 0; g < 4; g++)
#pragma unroll
                for (int s = 0; s < 2; s++) {
                    int c = ch*64 + g*16 + s*8 + (lane & 3)*2;
                    float2 bi = *(const float2*)(biou + jb + c);
                    *(float2*)(g_IOU + rlo*384 + jb + c) =
                        make_float2(acc[g][s][0] + bi.x, acc[g][s][1] + bi.y);
                    *(float2*)(g_IOU + rhi*384 + jb + c) =
                        make_float2(acc[g][s][2] + bi.x, acc[g][s][3] + bi.y);
                }
        }
    }
}

// ---------------- K3b: gates -> out ----------------
__global__ void k3b(float* __restrict__ out) {
    int idx = blockIdx.x * blockDim.x + threadIdx.x;
    if (idx >= NN*32) return;
    int n = idx >> 5;
    int j = (idx & 31) * 4;
    const float* r = g_IOU + (size_t)n * 384;
    float4 iv = *(const float4*)(r + j);
    float4 ov = *(const float4*)(r + 128 + j);
    float4 uv = *(const float4*)(r + 256 + j);
    float4 cr = *(const float4*)(g_cred + (size_t)n*128 + j);
    float4 hc, cc;
    {
        float ig, og, ug, c, h;
        ig = 1.f/(1.f+expf(-iv.x)); og = 1.f/(1.f+expf(-ov.x)); ug = tanhf(uv.x);
        c = ig*ug + cr.x; h = og*tanhf(c); hc.x = h; cc.x = c;
        ig = 1.f/(1.f+expf(-iv.y)); og = 1.f/(1.f+expf(-ov.y)); ug = tanhf(uv.y);
        c = ig*ug + cr.y; h = og*tanhf(c); hc.y = h; cc.y = c;
        ig = 1.f/(1.f+expf(-iv.z)); og = 1.f/(1.f+expf(-ov.z)); ug = tanhf(uv.z);
        c = ig*ug + cr.z; h = og*tanhf(c); hc.z = h; cc.z = c;
        ig = 1.f/(1.f+expf(-iv.w)); og = 1.f/(1.f+expf(-ov.w)); ug = tanhf(uv.w);
        c = ig*ug + cr.w; h = og*tanhf(c); hc.w = h; cc.w = c;
    }
    *(float4*)(out + (size_t)n*128 + j) = hc;
    *(float4*)(out + (size_t)NN*128 + (size_t)n*128 + j) = cc;
}

// ---------------- launcher ----------------
extern "C" void kernel_launch(void* const* d_in, const int* in_sizes, int n_in,
                              void* d_out, int out_size) {
    const float* x      = (const float*)d_in[0];
    const float* h_mail = (const float*)d_in[1];
    const float* c_mail = (const float*)d_in[2];
    const float* Wiou   = (const float*)d_in[3];
    const float* Uiou   = (const float*)d_in[4];
    const float* biou   = (const float*)d_in[5];
    const float* Of     = (const float*)d_in[6];
    const float* Zf     = (const float*)d_in[7];
    const float* Qf     = (const float*)d_in[8];
    const float* Kf     = (const float*)d_in[9];
    const float* vf     = (const float*)d_in[10];
    const float* Wa     = (const float*)d_in[11];
    const float* Wd     = (const float*)d_in[12];
    const float* Vf     = (const float*)d_in[13];
    const int*   etype  = (const int*)d_in[14];
    float* out = (float*)d_out;

    cudaFuncSetAttribute(k2a, cudaFuncAttributeMaxDynamicSharedMemorySize, K2A_SMEM);
    cudaFuncSetAttribute(k2b, cudaFuncAttributeMaxDynamicSharedMemorySize, K2B_SMEM);
    cudaFuncSetAttribute(k3a, cudaFuncAttributeMaxDynamicSharedMemorySize, K3_SMEM);

    k1a<<<384, 256>>>(Wa, Wd, Uiou);
    k1b<<<577, 256>>>(vf, Wiou, Qf, Vf);
    k1c<<<6250, 256>>>(x);
    k2a<<<148, 512, K2A_SMEM>>>(h_mail, Kf, Vf, etype);
    k2b<<<148, 512, K2B_SMEM>>>(h_mail, c_mail, Of, Zf, etype);
    k3a<<<dim3(3, 49), 512, K3_SMEM>>>(biou);
    k3b<<<6250, 256>>>(out);
}

// round 10
// speedup vs baseline: 1.9040x; 1.0808x over previous
#include <cuda_runtime.h>
#include <cuda_bf16.h>
#include <math.h>

#define NN 50000
#define HH 128
#define NPAD 50048            // 391*128, padded rows (zero-init)
#define TN 16                 // nodes per tile (16*8 = 128 rows)
#define NTILES (NN/TN)        // 3125

// ---------------- scratch (__device__ globals; zero-initialized) ----------------
__device__ float g_T[2*128*128];              // Q0 = vf@Wd | Q1 = vf@Wa
__device__ float g_G[384*384];                // [Q0@U0 ; Q1@U1 ; Wiou]
__device__ float g_qv[128];                   // Qf @ Vf
__device__ float g_px[NN];                    // x . qv  (per node)
__device__ __nv_bfloat16 g_Zh[(size_t)NPAD*384];  // Z hi (bf16 split)
__device__ __nv_bfloat16 g_Zl[(size_t)NPAD*384];  // Z lo
__device__ float g_IOU[(size_t)NPAD*384];
__device__ float g_cred[(size_t)NN*128];

// ================= helpers =================
__device__ __forceinline__ unsigned smem_u32(const void* p) {
    unsigned a;
    asm("{ .reg .u64 t; cvta.to.shared.u64 t, %1; cvt.u32.u64 %0, t; }" : "=r"(a) : "l"(p));
    return a;
}

__device__ __forceinline__ void ldsm4(unsigned r[4], unsigned addr) {
    asm volatile("ldmatrix.sync.aligned.m8n8.x4.shared.b16 {%0,%1,%2,%3}, [%4];"
                 : "=r"(r[0]), "=r"(r[1]), "=r"(r[2]), "=r"(r[3]) : "r"(addr));
}

__device__ __forceinline__ void mma16816(float c[4], const unsigned a[4],
                                         unsigned b0, unsigned b1) {
    asm volatile("mma.sync.aligned.m16n8k16.row.col.f32.bf16.bf16.f32 "
                 "{%0,%1,%2,%3}, {%4,%5,%6,%7}, {%8,%9}, {%0,%1,%2,%3};"
                 : "+f"(c[0]), "+f"(c[1]), "+f"(c[2]), "+f"(c[3])
                 : "r"(a[0]), "r"(a[1]), "r"(a[2]), "r"(a[3]), "r"(b0), "r"(b1));
}

// fp32 -> bf16 hi/lo split, 2 elements packed per word
__device__ __forceinline__ void split2(float a, float b, unsigned& hi, unsigned& lo) {
    __nv_bfloat16 ha = __float2bfloat16_rn(a);
    __nv_bfloat16 hb = __float2bfloat16_rn(b);
    __nv_bfloat16 la = __float2bfloat16_rn(a - __bfloat162float(ha));
    __nv_bfloat16 lb = __float2bfloat16_rn(b - __bfloat162float(hb));
    hi = ((unsigned)__bfloat16_as_ushort(hb) << 16) | (unsigned)__bfloat16_as_ushort(ha);
    lo = ((unsigned)__bfloat16_as_ushort(lb) << 16) | (unsigned)__bfloat16_as_ushort(la);
}

__device__ __forceinline__ float shflr(float v, int m) {
    return __shfl_xor_sync(0xffffffffu, v, m);
}

// ---------------- K1a: Q0 = vf@Wd, Q1 = vf@Wa (128x128 each) ----------------
__global__ void k1a(const float* __restrict__ Wa, const float* __restrict__ Wd,
                    const float* __restrict__ vf) {
    int idx = blockIdx.x * blockDim.x + threadIdx.x;
    if (idx >= 2*128*128) return;
    int which = idx >> 14;
    int rem   = idx & 16383;
    int m = rem >> 7, j = rem & 127;
    const float* W = which ? Wa : Wd;
    float s = 0.f;
#pragma unroll 8
    for (int z = 0; z < 128; z++) s += vf[m*128+z] * W[z*128+j];
    g_T[idx] = s;
}

// ---------------- K1b: G = [Q0@U0 ; Q1@U1 ; Wiou]; qv = Qf@Vf ----------------
__global__ void k1b(const float* __restrict__ Uiou, const float* __restrict__ Wiou,
                    const float* __restrict__ Qf, const float* __restrict__ Vf) {
    int idx = blockIdx.x * blockDim.x + threadIdx.x;
    if (idx < 2*128*384) {
        int which = idx / (128*384);
        int rem   = idx - which*(128*384);
        int m = rem / 384, j = rem - m*384;
        const float* Q = g_T + which*(128*128);
        const float* U = Uiou + which*(128*384);
        float s = 0.f;
#pragma unroll 8
        for (int z = 0; z < 128; z++) s += Q[m*128+z] * U[z*384+j];
        g_G[idx] = s;
    } else if (idx < 3*128*384) {
        int rem = idx - 2*128*384;
        g_G[idx] = Wiou[rem];
    } else if (idx < 3*128*384 + 128) {
        int m = idx - 3*128*384;
        float s = 0.f;
#pragma unroll 8
        for (int j = 0; j < 128; j++) s += Qf[m*128+j] * Vf[j];
        g_qv[m] = s;
    }
}

// ---------------- K1c: px = x . qv ; x -> Zh/Zl cols [256,384) ----------------
__global__ void k1c(const float* __restrict__ x) {
    int idx = blockIdx.x * blockDim.x + threadIdx.x;   // NN*32
    if (idx >= NN*32) return;
    int n = idx >> 5;
    int j = (idx & 31) * 4;
    float4 v = *(const float4*)(x + (size_t)n*128 + j);
    unsigned h0, l0, h1, l1;
    split2(v.x, v.y, h0, l0);
    split2(v.z, v.w, h1, l1);
    size_t o = (size_t)n*384 + 256 + j;
    *(unsigned*)(g_Zh + o)     = h0;
    *(unsigned*)(g_Zh + o + 2) = h1;
    *(unsigned*)(g_Zl + o)     = l0;
    *(unsigned*)(g_Zl + o + 2) = l1;
    float p = v.x*g_qv[j] + v.y*g_qv[j+1] + v.z*g_qv[j+2] + v.w*g_qv[j+3];
#pragma unroll
    for (int m = 1; m < 32; m <<= 1) p += shflr(p, m);
    if ((idx & 31) == 0) g_px[n] = p;
}

// ---------------- K2 (fused): hk-GEMM + f-GEMM over shared A tile ----------------
// Weights resident: Kh Kl Zh Zl Dh Dl (6 x 32KB). A chunk: Ah Al (2 x 16KB).
// p_buf aliases the A region (used only after all MMAs of a tile).
#define K2_AB   196608
#define K2_SMEM 229376
__global__ void __launch_bounds__(512, 1)
k2(const float* __restrict__ hmail, const float* __restrict__ cmail,
   const float* __restrict__ Kf, const float* __restrict__ Vf,
   const float* __restrict__ Of, const float* __restrict__ Zf,
   const int* __restrict__ etype) {
    extern __shared__ char smc[];
    const unsigned smb = smem_u32(smc);
    const int tid = threadIdx.x, wid = tid >> 5, lane = tid & 31;
    const int wrow = wid & 7, ch = wid >> 3;        // row stripe, col half
    const unsigned AB = smb + K2_AB;
    float* pb = (float*)(smc + K2_AB);              // alias (post-MMA only)

    // weight prep: B[n][k] = W[k][n]; bf16 hi/lo; row stride 256B, XOR swizzle
    for (int idx = tid; idx < 128*128; idx += 512) {
        int n = idx & 127, k = idx >> 7;
        unsigned off = (unsigned)(n*256 + ((2*k) ^ ((n & 7) << 4)));
        float kf = Kf[k*128 + n];
        __nv_bfloat16 kh = __float2bfloat16_rn(kf);
        __nv_bfloat16 kl = __float2bfloat16_rn(kf - __bfloat162float(kh));
        *(__nv_bfloat16*)(smc + 0*32768 + off) = kh;
        *(__nv_bfloat16*)(smc + 1*32768 + off) = kl;
        float zf = Zf[k*128 + n];
        float d  = Of[k*128 + n] - zf;
        __nv_bfloat16 zh = __float2bfloat16_rn(zf);
        __nv_bfloat16 zl = __float2bfloat16_rn(zf - __bfloat162float(zh));
        __nv_bfloat16 dh = __float2bfloat16_rn(d);
        __nv_bfloat16 dl = __float2bfloat16_rn(d - __bfloat162float(dh));
        *(__nv_bfloat16*)(smc + 2*32768 + off) = zh;
        *(__nv_bfloat16*)(smc + 3*32768 + off) = zl;
        *(__nv_bfloat16*)(smc + 4*32768 + off) = dh;
        *(__nv_bfloat16*)(smc + 5*32768 + off) = dl;
    }
    __syncthreads();

    for (int tile = blockIdx.x; tile < NTILES; tile += gridDim.x) {
        const size_t rbase = (size_t)tile * 128;

        const unsigned mlo = (etype[rbase + wrow*16 + (lane >> 2)]     != 0) ? 0xffffffffu : 0u;
        const unsigned mhi = (etype[rbase + wrow*16 + 8 + (lane >> 2)] != 0) ? 0xffffffffu : 0u;

        float acck[4][2][4], accf[4][2][4];
#pragma unroll
        for (int g = 0; g < 4; g++)
#pragma unroll
            for (int s = 0; s < 2; s++)
#pragma unroll
                for (int q = 0; q < 4; q++) { acck[g][s][q] = 0.f; accf[g][s][q] = 0.f; }

        for (int chunk = 0; chunk < 2; chunk++) {
            // convert A chunk [128 rows x 64 k] -> Ah/Al
            {
                const int row = tid >> 2, seg = tid & 3;
                const float* src = hmail + (rbase + row)*128 + chunk*64 + seg*16;
                const unsigned rsw = (unsigned)((row & 7) << 4);
#pragma unroll
                for (int i = 0; i < 4; i++) {
                    float4 v = ((const float4*)src)[i];
                    unsigned h0, l0, h1, l1;
                    split2(v.x, v.y, h0, l0);
                    split2(v.z, v.w, h1, l1);
                    int j = seg*16 + i*4;
                    unsigned bo = (unsigned)(row*128 + ((2*j) ^ rsw));
                    *(unsigned*)(smc + K2_AB + bo)             = h0;
                    *(unsigned*)(smc + K2_AB + bo + 4)         = h1;
                    *(unsigned*)(smc + K2_AB + 16384 + bo)     = l0;
                    *(unsigned*)(smc + K2_AB + 16384 + bo + 4) = l1;
                }
            }
            __syncthreads();
            // MMA: warp = rows wrow*16..+15, cols ch*64..+63; 9 terms
            {
                const int arow = wrow*16 + (lane & 7) + ((lane >> 3) & 1) * 8;
                const unsigned arsw = (unsigned)((arow & 7) << 4);
                const int bn_l = (lane & 7) + (lane >> 4) * 8;
                const int bkb_l = ((lane >> 3) & 1) * 16;
#pragma unroll
                for (int kk = 0; kk < 4; kk++) {
                    unsigned akb = (unsigned)(kk*32 + (lane >> 4) * 16);
                    unsigned aoff = (unsigned)(arow*128) + (akb ^ arsw);
                    unsigned ah[4], al[4], aeh[4], ael[4];
                    ldsm4(ah, AB + aoff);
                    ldsm4(al, AB + 16384 + aoff);
                    aeh[0] = ah[0] & mlo; aeh[1] = ah[1] & mhi;
                    aeh[2] = ah[2] & mlo; aeh[3] = ah[3] & mhi;
                    ael[0] = al[0] & mlo; ael[1] = al[1] & mhi;
                    ael[2] = al[2] & mlo; ael[3] = al[3] & mhi;
                    const int bkb = chunk*128 + kk*32 + bkb_l;
#pragma unroll
                    for (int g = 0; g < 4; g++) {
                        int bn = ch*64 + g*16 + bn_l;
                        unsigned boff = (unsigned)(bn*256) +
                                        ((unsigned)bkb ^ ((unsigned)(bn & 7) << 4));
                        unsigned kh[4], kl[4], zh[4], zl[4], dh[4], dl[4];
                        ldsm4(kh, smb + 0*32768 + boff);
                        ldsm4(kl, smb + 1*32768 + boff);
                        ldsm4(zh, smb + 2*32768 + boff);
                        ldsm4(zl, smb + 3*32768 + boff);
                        ldsm4(dh, smb + 4*32768 + boff);
                        ldsm4(dl, smb + 5*32768 + boff);
#pragma unroll
                        for (int s = 0; s < 2; s++) {
                            mma16816(acck[g][s], ah,  kh[s*2], kh[s*2+1]);
                            mma16816(acck[g][s], ah,  kl[s*2], kl[s*2+1]);
                            mma16816(acck[g][s], al,  kh[s*2], kh[s*2+1]);
                            mma16816(accf[g][s], ah,  zh[s*2], zh[s*2+1]);
                            mma16816(accf[g][s], ah,  zl[s*2], zl[s*2+1]);
                            mma16816(accf[g][s], al,  zh[s*2], zh[s*2+1]);
                            mma16816(accf[g][s], aeh, dh[s*2], dh[s*2+1]);
                            mma16816(accf[g][s], aeh, dl[s*2], dl[s*2+1]);
                            mma16816(accf[g][s], ael, dh[s*2], dh[s*2+1]);
                        }
                    }
                }
            }
            __syncthreads();
        }

        const int rlo = wrow*16 + (lane >> 2);     // local mail row (node0)
        const int rhi = rlo + 8;                   // node1
        const int node0 = tile*TN + wrow*2, node1 = node0 + 1;

        // ---- f epilogue: f = sigmoid(accf); c_red = sum over 8 mail rows ----
#pragma unroll
        for (int g = 0; g < 4; g++)
#pragma unroll
            for (int s = 0; s < 2; s++) {
                int col = ch*64 + g*16 + s*8 + (lane & 3)*2;
                float2 c0 = *(const float2*)(cmail + (rbase + rlo)*128 + col);
                float2 c1 = *(const float2*)(cmail + (rbase + rhi)*128 + col);
                float v0 = c0.x / (1.f + expf(-accf[g][s][0]));
                float v1 = c0.y / (1.f + expf(-accf[g][s][1]));
                float v2 = c1.x / (1.f + expf(-accf[g][s][2]));
                float v3 = c1.y / (1.f + expf(-accf[g][s][3]));
#pragma unroll
                for (int m = 4; m < 32; m <<= 1) {
                    v0 += shflr(v0, m); v1 += shflr(v1, m);
                    v2 += shflr(v2, m); v3 += shflr(v3, m);
                }
                if (lane < 4) {
                    int c = ch*64 + g*16 + s*8 + lane*2;
                    *(float2*)(g_cred + (size_t)node0*128 + c) = make_float2(v0, v1);
                } else if (lane < 8) {
                    int c = ch*64 + g*16 + s*8 + (lane - 4)*2;
                    *(float2*)(g_cred + (size_t)node1*128 + c) = make_float2(v2, v3);
                }
            }

        // ---- k epilogue: softmax over mails, weighted sums -> g_Zh/g_Zl ----
        float plo = 0.f, phi = 0.f;
#pragma unroll
        for (int g = 0; g < 4; g++)
#pragma unroll
            for (int s = 0; s < 2; s++) {
                int c = ch*64 + g*16 + s*8 + (lane & 3)*2;
                float vf0 = __ldg(Vf + c), vf1 = __ldg(Vf + c + 1);
                plo += acck[g][s][0]*vf0 + acck[g][s][1]*vf1;
                phi += acck[g][s][2]*vf0 + acck[g][s][3]*vf1;
            }
        plo += shflr(plo, 1); plo += shflr(plo, 2);
        phi += shflr(phi, 1); phi += shflr(phi, 2);
        if ((lane & 3) == 0) {
            pb[ch*128 + rlo] = plo;
            pb[ch*128 + rhi] = phi;
        }
        __syncthreads();
        float p_lo = pb[rlo] + pb[128 + rlo];
        float p_hi = pb[rhi] + pb[128 + rhi];

        float e_lo = (float)etype[rbase + rlo];
        float e_hi = (float)etype[rbase + rhi];
        float sc_lo = tanhf(g_px[node0] + p_lo);
        float sc_hi = tanhf(g_px[node1] + p_hi);

        float mx0 = sc_lo, mx1 = sc_hi, se0, se1, sm0 = e_lo, sm1 = e_hi;
#pragma unroll
        for (int m = 4; m < 32; m <<= 1) {
            mx0 = fmaxf(mx0, shflr(mx0, m));
            mx1 = fmaxf(mx1, shflr(mx1, m));
            sm0 += shflr(sm0, m);
            sm1 += shflr(sm1, m);
        }
        float ex0 = expf(sc_lo - mx0), ex1 = expf(sc_hi - mx1);
        se0 = ex0; se1 = ex1;
#pragma unroll
        for (int m = 4; m < 32; m <<= 1) { se0 += shflr(se0, m); se1 += shflr(se1, m); }
        float w0 = ex0 / se0, w1 = ex1 / se1;
        float mod0 = sm0 * 0.125f, mod1 = sm1 * 0.125f;
        float c1_lo = w0 * (1.f - mod0) * e_lo;
        float c0_lo = w0 * mod0 * (1.f - e_lo);
        float c1_hi = w1 * (1.f - mod1) * e_hi;
        float c0_hi = w1 * mod1 * (1.f - e_hi);

#pragma unroll
        for (int g = 0; g < 4; g++)
#pragma unroll
            for (int s = 0; s < 2; s++) {
                float b00 = c0_lo*acck[g][s][0], b01 = c0_lo*acck[g][s][1];
                float a00 = c1_lo*acck[g][s][0], a01 = c1_lo*acck[g][s][1];
                float b10 = c0_hi*acck[g][s][2], b11 = c0_hi*acck[g][s][3];
                float a10 = c1_hi*acck[g][s][2], a11 = c1_hi*acck[g][s][3];
#pragma unroll
                for (int m = 4; m < 32; m <<= 1) {
                    b00 += shflr(b00, m); b01 += shflr(b01, m);
                    a00 += shflr(a00, m); a01 += shflr(a01, m);
                    b10 += shflr(b10, m); b11 += shflr(b11, m);
                    a10 += shflr(a10, m); a11 += shflr(a11, m);
                }
                if (lane < 4) {
                    int c = ch*64 + g*16 + s*8 + lane*2;
                    size_t ro = (size_t)node0 * 384;
                    unsigned hi, lo;
                    split2(b00, b01, hi, lo);
                    *(unsigned*)(g_Zh + ro + c) = hi;
                    *(unsigned*)(g_Zl + ro + c) = lo;
                    split2(a00, a01, hi, lo);
                    *(unsigned*)(g_Zh + ro + 128 + c) = hi;
                    *(unsigned*)(g_Zl + ro + 128 + c) = lo;
                } else if (lane < 8) {
                    int c = ch*64 + g*16 + s*8 + (lane - 4)*2;
                    size_t ro = (size_t)node1 * 384;
                    unsigned hi, lo;
                    split2(b10, b11, hi, lo);
                    *(unsigned*)(g_Zh + ro + c) = hi;
                    *(unsigned*)(g_Zl + ro + c) = lo;
                    split2(a10, a11, hi, lo);
                    *(unsigned*)(g_Zh + ro + 128 + c) = hi;
                    *(unsigned*)(g_Zl + ro + 128 + c) = lo;
                }
            }
        __syncthreads();   // protect pb / A region before next tile's convert
    }
}

// ---------------- K3a (mma.sync bf16, 3-term split): IOU = Z @ G + biou ----------------
// SMEM: Bh 96K | Bl 96K | Ah 16K | Al 16K  = 229376 B
#define K3_BL   98304
#define K3_AB   196608
#define K3_SMEM (196608 + 32768)
__global__ void __launch_bounds__(512, 1)
k3a(const float* __restrict__ biou) {
    extern __shared__ char smc[];
    const unsigned smb = smem_u32(smc);
    const int tid = threadIdx.x, wid = tid >> 5, lane = tid & 31;
    const int wrow = wid & 7, ch = wid >> 3;
    const int jb = blockIdx.x * 128;           // output col block
    const unsigned AB = smb + K3_AB;

    // B fill: B[n][k] = G[k][jb+n], bf16 hi/lo, row stride 768B, XOR swizzle
    for (int idx = tid; idx < 128*384; idx += 512) {
        int k = idx % 384, n = idx / 384;
        float v = g_G[k*384 + jb + n];
        __nv_bfloat16 bh = __float2bfloat16_rn(v);
        __nv_bfloat16 bl = __float2bfloat16_rn(v - __bfloat162float(bh));
        unsigned off = (unsigned)(n*768 + ((2*k) ^ ((n & 7) << 4)));
        *(__nv_bfloat16*)(smc + off)          = bh;
        *(__nv_bfloat16*)(smc + K3_BL + off)  = bl;
    }
    __syncthreads();

    for (int rt = blockIdx.y; rt < 391; rt += gridDim.y) {
        const size_t rbase = (size_t)rt * 128;

        float acc[4][2][4];
#pragma unroll
        for (int g = 0; g < 4; g++)
#pragma unroll
            for (int s = 0; s < 2; s++)
#pragma unroll
                for (int q = 0; q < 4; q++) acc[g][s][q] = 0.f;

        for (int chunk = 0; chunk < 6; chunk++) {
            {
                const int row = tid >> 2, seg = tid & 3;
                const size_t go = (rbase + row)*384 + chunk*64 + seg*16;
                const unsigned rsw = (unsigned)((row & 7) << 4);
#pragma unroll
                for (int i = 0; i < 2; i++) {
                    uint4 h = *(const uint4*)(g_Zh + go + i*8);
                    uint4 l = *(const uint4*)(g_Zl + go + i*8);
                    int j = seg*16 + i*8;
                    unsigned bo = (unsigned)(row*128 + ((2*j) ^ rsw));
                    *(uint4*)(smc + K3_AB + bo)         = h;
                    *(uint4*)(smc + K3_AB + 16384 + bo) = l;
                }
            }
            __syncthreads();
            {
                const int arow = wrow*16 + (lane & 7) + ((lane >> 3) & 1) * 8;
                const unsigned arsw = (unsigned)((arow & 7) << 4);
                const int bn_l = (lane & 7) + (lane >> 4) * 8;
                const int bkb_l = ((lane >> 3) & 1) * 16;
#pragma unroll
                for (int kk = 0; kk < 4; kk++) {
                    unsigned akb = (unsigned)(kk*32 + (lane >> 4) * 16);
                    unsigned aoff = (unsigned)(arow*128) + (akb ^ arsw);
                    unsigned ah[4], al[4];
                    ldsm4(ah, AB + aoff);
                    ldsm4(al, AB + 16384 + aoff);
                    const int bkb = chunk*128 + kk*32 + bkb_l;
#pragma unroll
                    for (int g = 0; g < 4; g++) {
                        int bn = ch*64 + g*16 + bn_l;
                        unsigned boff = (unsigned)(bn*768) +
                                        ((unsigned)bkb ^ ((unsigned)(bn & 7) << 4));
                        unsigned bh[4], bl[4];
                        ldsm4(bh, smb + boff);
                        ldsm4(bl, smb + K3_BL + boff);
#pragma unroll
                        for (int s = 0; s < 2; s++) {
                            mma16816(acc[g][s], ah, bh[s*2], bh[s*2+1]);
                            mma16816(acc[g][s], ah, bl[s*2], bl[s*2+1]);
                            mma16816(acc[g][s], al, bh[s*2], bh[s*2+1]);
                        }
                    }
                }
            }
            __syncthreads();
        }

        {
            const size_t rlo = rbase + wrow*16 + (lane >> 2);
            const size_t rhi = rlo + 8;
#pragma unroll
            for (int g = 0; g < 4; g++)
#pragma unroll
                for (int s = 0; s < 2; s++) {
                    int c = ch*64 + g*16 + s*8 + (lane & 3)*2;
                    float2 bi = *(const float2*)(biou + jb + c);
                    *(float2*)(g_IOU + rlo*384 + jb + c) =
                        make_float2(acc[g][s][0] + bi.x, acc[g][s][1] + bi.y);
                    *(float2*)(g_IOU + rhi*384 + jb + c) =
                        make_float2(acc[g][s][2] + bi.x, acc[g][s][3] + bi.y);
                }
        }
    }
}

// ---------------- K3b: gates -> out ----------------
__global__ void k3b(float* __restrict__ out) {
    int idx = blockIdx.x * blockDim.x + threadIdx.x;
    if (idx >= NN*32) return;
    int n = idx >> 5;
    int j = (idx & 31) * 4;
    const float* r = g_IOU + (size_t)n * 384;
    float4 iv = *(const float4*)(r + j);
    float4 ov = *(const float4*)(r + 128 + j);
    float4 uv = *(const float4*)(r + 256 + j);
    float4 cr = *(const float4*)(g_cred + (size_t)n*128 + j);
    float4 hc, cc;
    {
        float ig, og, ug, c, h;
        ig = 1.f/(1.f+expf(-iv.x)); og = 1.f/(1.f+expf(-ov.x)); ug = tanhf(uv.x);
        c = ig*ug + cr.x; h = og*tanhf(c); hc.x = h; cc.x = c;
        ig = 1.f/(1.f+expf(-iv.y)); og = 1.f/(1.f+expf(-ov.y)); ug = tanhf(uv.y);
        c = ig*ug + cr.y; h = og*tanhf(c); hc.y = h; cc.y = c;
        ig = 1.f/(1.f+expf(-iv.z)); og = 1.f/(1.f+expf(-ov.z)); ug = tanhf(uv.z);
        c = ig*ug + cr.z; h = og*tanhf(c); hc.z = h; cc.z = c;
        ig = 1.f/(1.f+expf(-iv.w)); og = 1.f/(1.f+expf(-ov.w)); ug = tanhf(uv.w);
        c = ig*ug + cr.w; h = og*tanhf(c); hc.w = h; cc.w = c;
    }
    *(float4*)(out + (size_t)n*128 + j) = hc;
    *(float4*)(out + (size_t)NN*128 + (size_t)n*128 + j) = cc;
}

// ---------------- launcher ----------------
extern "C" void kernel_launch(void* const* d_in, const int* in_sizes, int n_in,
                              void* d_out, int out_size) {
    const float* x      = (const float*)d_in[0];
    const float* h_mail = (const float*)d_in[1];
    const float* c_mail = (const float*)d_in[2];
    const float* Wiou   = (const float*)d_in[3];
    const float* Uiou   = (const float*)d_in[4];
    const float* biou   = (const float*)d_in[5];
    const float* Of     = (const float*)d_in[6];
    const float* Zf     = (const float*)d_in[7];
    const float* Qf     = (const float*)d_in[8];
    const float* Kf     = (const float*)d_in[9];
    const float* vf     = (const float*)d_in[10];
    const float* Wa     = (const float*)d_in[11];
    const float* Wd     = (const float*)d_in[12];
    const float* Vf     = (const float*)d_in[13];
    const int*   etype  = (const int*)d_in[14];
    float* out = (float*)d_out;

    cudaFuncSetAttribute(k2,  cudaFuncAttributeMaxDynamicSharedMemorySize, K2_SMEM);
    cudaFuncSetAttribute(k3a, cudaFuncAttributeMaxDynamicSharedMemorySize, K3_SMEM);

    k1a<<<128, 256>>>(Wa, Wd, vf);
    k1b<<<577, 256>>>(Uiou, Wiou, Qf, Vf);
    k1c<<<6250, 256>>>(x);
    k2<<<148, 512, K2_SMEM>>>(h_mail, c_mail, Kf, Vf, Of, Zf, etype);
    k3a<<<dim3(3, 49), 512, K3_SMEM>>>(biou);
    k3b<<<6250, 256>>>(out);
}

// round 12
// speedup vs baseline: 2.0337x; 1.0681x over previous
#include <cuda_runtime.h>
#include <cuda_bf16.h>
#include <math.h>

#define NN 50000
#define HH 128
#define NPAD 50048            // 391*128, padded rows (zero-init)
#define TN 16                 // nodes per tile (16*8 = 128 rows)
#define NTILES (NN/TN)        // 3125

// ---------------- scratch (__device__ globals; zero-initialized) ----------------
__device__ float g_T[2*128*128];              // Q0 = vf@Wd | Q1 = vf@Wa
__device__ float g_G[384*384];                // [Q0@U0 ; Q1@U1 ; Wiou]
__device__ float g_qv[128];                   // Qf @ Vf
__device__ float g_px[NN];                    // x . qv  (per node)
__device__ __nv_bfloat16 g_Zh[(size_t)NPAD*384];  // Z hi (bf16 split)
__device__ __nv_bfloat16 g_Zl[(size_t)NPAD*384];  // Z lo
__device__ float g_IOU[(size_t)NPAD*384];
__device__ float g_cred[(size_t)NN*128];

// ================= helpers =================
__device__ __forceinline__ unsigned smem_u32(const void* p) {
    unsigned a;
    asm("{ .reg .u64 t; cvta.to.shared.u64 t, %1; cvt.u32.u64 %0, t; }" : "=r"(a) : "l"(p));
    return a;
}

__device__ __forceinline__ void ldsm4(unsigned r[4], unsigned addr) {
    asm volatile("ldmatrix.sync.aligned.m8n8.x4.shared.b16 {%0,%1,%2,%3}, [%4];"
                 : "=r"(r[0]), "=r"(r[1]), "=r"(r[2]), "=r"(r[3]) : "r"(addr));
}

__device__ __forceinline__ void mma16816(float c[4], const unsigned a[4],
                                         unsigned b0, unsigned b1) {
    asm volatile("mma.sync.aligned.m16n8k16.row.col.f32.bf16.bf16.f32 "
                 "{%0,%1,%2,%3}, {%4,%5,%6,%7}, {%8,%9}, {%0,%1,%2,%3};"
                 : "+f"(c[0]), "+f"(c[1]), "+f"(c[2]), "+f"(c[3])
                 : "r"(a[0]), "r"(a[1]), "r"(a[2]), "r"(a[3]), "r"(b0), "r"(b1));
}

#define CP_ASYNC16(dst, src) \
    asm volatile("cp.async.cg.shared.global [%0], [%1], 16;" :: "r"(dst), "l"(src) : "memory")
#define CP_COMMIT()  asm volatile("cp.async.commit_group;" ::: "memory")
#define CP_WAIT1()   asm volatile("cp.async.wait_group 1;" ::: "memory")
#define CP_WAIT0()   asm volatile("cp.async.wait_group 0;" ::: "memory")

// fp32 -> bf16 hi/lo split, 2 elements packed per word
__device__ __forceinline__ void split2(float a, float b, unsigned& hi, unsigned& lo) {
    __nv_bfloat16 ha = __float2bfloat16_rn(a);
    __nv_bfloat16 hb = __float2bfloat16_rn(b);
    __nv_bfloat16 la = __float2bfloat16_rn(a - __bfloat162float(ha));
    __nv_bfloat16 lb = __float2bfloat16_rn(b - __bfloat162float(hb));
    hi = ((unsigned)__bfloat16_as_ushort(hb) << 16) | (unsigned)__bfloat16_as_ushort(ha);
    lo = ((unsigned)__bfloat16_as_ushort(lb) << 16) | (unsigned)__bfloat16_as_ushort(la);
}

__device__ __forceinline__ float shflr(float v, int m) {
    return __shfl_xor_sync(0xffffffffu, v, m);
}

// ---------------- K1a: Q0 = vf@Wd, Q1 = vf@Wa (128x128 each) ----------------
__global__ void k1a(const float* __restrict__ Wa, const float* __restrict__ Wd,
                    const float* __restrict__ vf) {
    int idx = blockIdx.x * blockDim.x + threadIdx.x;
    if (idx >= 2*128*128) return;
    int which = idx >> 14;
    int rem   = idx & 16383;
    int m = rem >> 7, j = rem & 127;
    const float* W = which ? Wa : Wd;
    float s = 0.f;
#pragma unroll 8
    for (int z = 0; z < 128; z++) s += vf[m*128+z] * W[z*128+j];
    g_T[idx] = s;
}

// ---------------- K1b: G = [Q0@U0 ; Q1@U1 ; Wiou]; qv = Qf@Vf ----------------
__global__ void k1b(const float* __restrict__ Uiou, const float* __restrict__ Wiou,
                    const float* __restrict__ Qf, const float* __restrict__ Vf) {
    int idx = blockIdx.x * blockDim.x + threadIdx.x;
    if (idx < 2*128*384) {
        int which = idx / (128*384);
        int rem   = idx - which*(128*384);
        int m = rem / 384, j = rem - m*384;
        const float* Q = g_T + which*(128*128);
        const float* U = Uiou + which*(128*384);
        float s = 0.f;
#pragma unroll 8
        for (int z = 0; z < 128; z++) s += Q[m*128+z] * U[z*384+j];
        g_G[idx] = s;
    } else if (idx < 3*128*384) {
        int rem = idx - 2*128*384;
        g_G[idx] = Wiou[rem];
    } else if (idx < 3*128*384 + 128) {
        int m = idx - 3*128*384;
        float s = 0.f;
#pragma unroll 8
        for (int j = 0; j < 128; j++) s += Qf[m*128+j] * Vf[j];
        g_qv[m] = s;
    }
}

// ---------------- K1c: px = x . qv ; x -> Zh/Zl cols [256,384) ----------------
__global__ void k1c(const float* __restrict__ x) {
    int idx = blockIdx.x * blockDim.x + threadIdx.x;   // NN*32
    if (idx >= NN*32) return;
    int n = idx >> 5;
    int j = (idx & 31) * 4;
    float4 v = *(const float4*)(x + (size_t)n*128 + j);
    unsigned h0, l0, h1, l1;
    split2(v.x, v.y, h0, l0);
    split2(v.z, v.w, h1, l1);
    size_t o = (size_t)n*384 + 256 + j;
    *(unsigned*)(g_Zh + o)     = h0;
    *(unsigned*)(g_Zh + o + 2) = h1;
    *(unsigned*)(g_Zl + o)     = l0;
    *(unsigned*)(g_Zl + o + 2) = l1;
    float p = v.x*g_qv[j] + v.y*g_qv[j+1] + v.z*g_qv[j+2] + v.w*g_qv[j+3];
#pragma unroll
    for (int m = 1; m < 32; m <<= 1) p += shflr(p, m);
    if ((idx & 31) == 0) g_px[n] = p;
}

// ---------------- K2 (fused, software-pipelined) ----------------
// Weights resident: Kh Kl Zh Zl Dh Dl (6 x 32KB). A: 2 buffers x (Ah 8K + Al 8K).
// 4 sub-chunks of 32 k per tile; h_mail prefetched into registers during MMA.
// A buffer layout: row stride 64B, 16B-slot swizzle s = u ^ ((row>>1)&3).
#define K2_AB   196608
#define K2_SMEM 229376
__global__ void __launch_bounds__(512, 1)
k2(const float* __restrict__ hmail, const float* __restrict__ cmail,
   const float* __restrict__ Kf, const float* __restrict__ Vf,
   const float* __restrict__ Of, const float* __restrict__ Zf,
   const int* __restrict__ etype) {
    extern __shared__ char smc[];
    const unsigned smb = smem_u32(smc);
    const int tid = threadIdx.x, wid = tid >> 5, lane = tid & 31;
    const int wrow = wid & 7, ch = wid >> 3;        // row stripe, col half
    float* pb = (float*)(smc + K2_AB);              // alias buf0 (post-MMA use only)

    // weight prep: B[n][k] = W[k][n]; bf16 hi/lo; row stride 256B, XOR swizzle
    for (int idx = tid; idx < 128*128; idx += 512) {
        int n = idx & 127, k = idx >> 7;
        unsigned off = (unsigned)(n*256 + ((2*k) ^ ((n & 7) << 4)));
        float kf = Kf[k*128 + n];
        __nv_bfloat16 kh = __float2bfloat16_rn(kf);
        __nv_bfloat16 kl = __float2bfloat16_rn(kf - __bfloat162float(kh));
        *(__nv_bfloat16*)(smc + 0*32768 + off) = kh;
        *(__nv_bfloat16*)(smc + 1*32768 + off) = kl;
        float zf = Zf[k*128 + n];
        float d  = Of[k*128 + n] - zf;
        __nv_bfloat16 zh = __float2bfloat16_rn(zf);
        __nv_bfloat16 zl = __float2bfloat16_rn(zf - __bfloat162float(zh));
        __nv_bfloat16 dh = __float2bfloat16_rn(d);
        __nv_bfloat16 dl = __float2bfloat16_rn(d - __bfloat162float(dh));
        *(__nv_bfloat16*)(smc + 2*32768 + off) = zh;
        *(__nv_bfloat16*)(smc + 3*32768 + off) = zl;
        *(__nv_bfloat16*)(smc + 4*32768 + off) = dh;
        *(__nv_bfloat16*)(smc + 5*32768 + off) = dl;
    }
    __syncthreads();

    const int crow = tid >> 2, cseg = tid & 3;          // convert mapping
    const unsigned csw = ((unsigned)((crow >> 1) & 3)) << 4;
    const unsigned cbo = (unsigned)(crow*64) + (((unsigned)cseg*16) ^ csw);

    float4 pf0, pf1;                                    // prefetch registers
    {   // initial prefetch: first tile, chunk 0
        if (blockIdx.x < NTILES) {
            const float* s = hmail + ((size_t)blockIdx.x*128 + crow)*128 + cseg*8;
            pf0 = ((const float4*)s)[0];
            pf1 = ((const float4*)s)[1];
        }
    }

    for (int tile = blockIdx.x; tile < NTILES; tile += gridDim.x) {
        const size_t rbase = (size_t)tile * 128;

        const unsigned mlo = (etype[rbase + wrow*16 + (lane >> 2)]     != 0) ? 0xffffffffu : 0u;
        const unsigned mhi = (etype[rbase + wrow*16 + 8 + (lane >> 2)] != 0) ? 0xffffffffu : 0u;

        float acck[4][2][4], accf[4][2][4];
#pragma unroll
        for (int g = 0; g < 4; g++)
#pragma unroll
            for (int s = 0; s < 2; s++)
#pragma unroll
                for (int q = 0; q < 4; q++) { acck[g][s][q] = 0.f; accf[g][s][q] = 0.f; }

#pragma unroll
        for (int c = 0; c < 4; c++) {
            // ---- convert current chunk from prefetch regs into A buf (c&1) ----
            {
                unsigned h0,l0,h1,l1,h2,l2,h3,l3;
                split2(pf0.x, pf0.y, h0, l0);
                split2(pf0.z, pf0.w, h1, l1);
                split2(pf1.x, pf1.y, h2, l2);
                split2(pf1.z, pf1.w, h3, l3);
                char* base = smc + K2_AB + (c & 1)*16384;
                *(uint4*)(base + cbo)        = make_uint4(h0, h1, h2, h3);
                *(uint4*)(base + 8192 + cbo) = make_uint4(l0, l1, l2, l3);
            }
            // ---- prefetch next chunk (or next tile's chunk 0) ----
            {
                int nt = (c < 3) ? tile : tile + (int)gridDim.x;
                int nc = (c + 1) & 3;
                if (nt < NTILES) {
                    const float* s = hmail + ((size_t)nt*128 + crow)*128 + nc*32 + cseg*8;
                    pf0 = ((const float4*)s)[0];
                    pf1 = ((const float4*)s)[1];
                }
            }
            __syncthreads();
            // ---- MMA on chunk c (32 k = 2 kk steps) ----
            {
                const int arow = wrow*16 + (lane & 7) + ((lane >> 3) & 1) * 8;
                const unsigned arsw = ((unsigned)((arow >> 1) & 3)) << 4;
                const int bn_l = (lane & 7) + (lane >> 4) * 8;
                const int bkb_l = ((lane >> 3) & 1) * 16;
                const unsigned abase = smb + K2_AB + (unsigned)((c & 1)*16384);
#pragma unroll
                for (int kk = 0; kk < 2; kk++) {
                    unsigned akb = (unsigned)(kk*32 + (lane >> 4) * 16);
                    unsigned aoff = (unsigned)(arow*64) + (akb ^ arsw);
                    unsigned ah[4], al[4], aeh[4], ael[4];
                    ldsm4(ah, abase + aoff);
                    ldsm4(al, abase + 8192 + aoff);
                    aeh[0] = ah[0] & mlo; aeh[1] = ah[1] & mhi;
                    aeh[2] = ah[2] & mlo; aeh[3] = ah[3] & mhi;
                    ael[0] = al[0] & mlo; ael[1] = al[1] & mhi;
                    ael[2] = al[2] & mlo; ael[3] = al[3] & mhi;
                    const int bkb = c*64 + kk*32 + bkb_l;
#pragma unroll
                    for (int g = 0; g < 4; g++) {
                        int bn = ch*64 + g*16 + bn_l;
                        unsigned boff = (unsigned)(bn*256) +
                                        ((unsigned)bkb ^ ((unsigned)(bn & 7) << 4));
                        unsigned kh[4], kl[4], zh[4], zl[4], dh[4], dl[4];
                        ldsm4(kh, smb + 0*32768 + boff);
                        ldsm4(kl, smb + 1*32768 + boff);
                        ldsm4(zh, smb + 2*32768 + boff);
                        ldsm4(zl, smb + 3*32768 + boff);
                        ldsm4(dh, smb + 4*32768 + boff);
                        ldsm4(dl, smb + 5*32768 + boff);
#pragma unroll
                        for (int s = 0; s < 2; s++) {
                            mma16816(acck[g][s], ah,  kh[s*2], kh[s*2+1]);
                            mma16816(acck[g][s], ah,  kl[s*2], kl[s*2+1]);
                            mma16816(acck[g][s], al,  kh[s*2], kh[s*2+1]);
                            mma16816(accf[g][s], ah,  zh[s*2], zh[s*2+1]);
                            mma16816(accf[g][s], ah,  zl[s*2], zl[s*2+1]);
                            mma16816(accf[g][s], al,  zh[s*2], zh[s*2+1]);
                            mma16816(accf[g][s], aeh, dh[s*2], dh[s*2+1]);
                            mma16816(accf[g][s], aeh, dl[s*2], dl[s*2+1]);
                            mma16816(accf[g][s], ael, dh[s*2], dh[s*2+1]);
                        }
                    }
                }
            }
        }

        const int rlo = wrow*16 + (lane >> 2);     // local mail row (node0)
        const int rhi = rlo + 8;                   // node1
        const int node0 = tile*TN + wrow*2, node1 = node0 + 1;

        // ---- f epilogue: f = sigmoid(accf); c_red = sum over 8 mail rows ----
#pragma unroll
        for (int g = 0; g < 4; g++)
#pragma unroll
            for (int s = 0; s < 2; s++) {
                int col = ch*64 + g*16 + s*8 + (lane & 3)*2;
                float2 c0 = *(const float2*)(cmail + (rbase + rlo)*128 + col);
                float2 c1 = *(const float2*)(cmail + (rbase + rhi)*128 + col);
                float v0 = c0.x / (1.f + expf(-accf[g][s][0]));
                float v1 = c0.y / (1.f + expf(-accf[g][s][1]));
                float v2 = c1.x / (1.f + expf(-accf[g][s][2]));
                float v3 = c1.y / (1.f + expf(-accf[g][s][3]));
#pragma unroll
                for (int m = 4; m < 32; m <<= 1) {
                    v0 += shflr(v0, m); v1 += shflr(v1, m);
                    v2 += shflr(v2, m); v3 += shflr(v3, m);
                }
                if (lane < 4) {
                    int c = ch*64 + g*16 + s*8 + lane*2;
                    *(float2*)(g_cred + (size_t)node0*128 + c) = make_float2(v0, v1);
                } else if (lane < 8) {
                    int c = ch*64 + g*16 + s*8 + (lane - 4)*2;
                    *(float2*)(g_cred + (size_t)node1*128 + c) = make_float2(v2, v3);
                }
            }

        // ---- k epilogue: softmax over mails, weighted sums -> g_Zh/g_Zl ----
        float plo = 0.f, phi = 0.f;
#pragma unroll
        for (int g = 0; g < 4; g++)
#pragma unroll
            for (int s = 0; s < 2; s++) {
                int c = ch*64 + g*16 + s*8 + (lane & 3)*2;
                float vf0 = __ldg(Vf + c), vf1 = __ldg(Vf + c + 1);
                plo += acck[g][s][0]*vf0 + acck[g][s][1]*vf1;
                phi += acck[g][s][2]*vf0 + acck[g][s][3]*vf1;
            }
        plo += shflr(plo, 1); plo += shflr(plo, 2);
        phi += shflr(phi, 1); phi += shflr(phi, 2);
        if ((lane & 3) == 0) {
            pb[ch*128 + rlo] = plo;
            pb[ch*128 + rhi] = phi;
        }
        __syncthreads();
        float p_lo = pb[rlo] + pb[128 + rlo];
        float p_hi = pb[rhi] + pb[128 + rhi];

        float e_lo = (float)etype[rbase + rlo];
        float e_hi = (float)etype[rbase + rhi];
        float sc_lo = tanhf(g_px[node0] + p_lo);
        float sc_hi = tanhf(g_px[node1] + p_hi);

        float mx0 = sc_lo, mx1 = sc_hi, se0, se1, sm0 = e_lo, sm1 = e_hi;
#pragma unroll
        for (int m = 4; m < 32; m <<= 1) {
            mx0 = fmaxf(mx0, shflr(mx0, m));
            mx1 = fmaxf(mx1, shflr(mx1, m));
            sm0 += shflr(sm0, m);
            sm1 += shflr(sm1, m);
        }
        float ex0 = expf(sc_lo - mx0), ex1 = expf(sc_hi - mx1);
        se0 = ex0; se1 = ex1;
#pragma unroll
        for (int m = 4; m < 32; m <<= 1) { se0 += shflr(se0, m); se1 += shflr(se1, m); }
        float w0 = ex0 / se0, w1 = ex1 / se1;
        float mod0 = sm0 * 0.125f, mod1 = sm1 * 0.125f;
        float c1_lo = w0 * (1.f - mod0) * e_lo;
        float c0_lo = w0 * mod0 * (1.f - e_lo);
        float c1_hi = w1 * (1.f - mod1) * e_hi;
        float c0_hi = w1 * mod1 * (1.f - e_hi);

#pragma unroll
        for (int g = 0; g < 4; g++)
#pragma unroll
            for (int s = 0; s < 2; s++) {
                float b00 = c0_lo*acck[g][s][0], b01 = c0_lo*acck[g][s][1];
                float a00 = c1_lo*acck[g][s][0], a01 = c1_lo*acck[g][s][1];
                float b10 = c0_hi*acck[g][s][2], b11 = c0_hi*acck[g][s][3];
                float a10 = c1_hi*acck[g][s][2], a11 = c1_hi*acck[g][s][3];
#pragma unroll
                for (int m = 4; m < 32; m <<= 1) {
                    b00 += shflr(b00, m); b01 += shflr(b01, m);
                    a00 += shflr(a00, m); a01 += shflr(a01, m);
                    b10 += shflr(b10, m); b11 += shflr(b11, m);
                    a10 += shflr(a10, m); a11 += shflr(a11, m);
                }
                if (lane < 4) {
                    int c = ch*64 + g*16 + s*8 + lane*2;
                    size_t ro = (size_t)node0 * 384;
                    unsigned hi, lo;
                    split2(b00, b01, hi, lo);
                    *(unsigned*)(g_Zh + ro + c) = hi;
                    *(unsigned*)(g_Zl + ro + c) = lo;
                    split2(a00, a01, hi, lo);
                    *(unsigned*)(g_Zh + ro + 128 + c) = hi;
                    *(unsigned*)(g_Zl + ro + 128 + c) = lo;
                } else if (lane < 8) {
                    int c = ch*64 + g*16 + s*8 + (lane - 4)*2;
                    size_t ro = (size_t)node1 * 384;
                    unsigned hi, lo;
                    split2(b10, b11, hi, lo);
                    *(unsigned*)(g_Zh + ro + c) = hi;
                    *(unsigned*)(g_Zl + ro + c) = lo;
                    split2(a10, a11, hi, lo);
                    *(unsigned*)(g_Zh + ro + 128 + c) = hi;
                    *(unsigned*)(g_Zl + ro + 128 + c) = lo;
                }
            }
        __syncthreads();   // pb (aliases buf0) must be fully read before next conv(0)
    }
}

// ---------------- K3a (mma.sync bf16, 3-term, cp.async double-buffered A) ----------------
// SMEM: Bh 96K | Bl 96K | A bufs 2 x (Ah 8K + Al 8K) = 229376 B
#define K3_BL   98304
#define K3_AB   196608
#define K3_SMEM 229376
__global__ void __launch_bounds__(512, 1)
k3a(const float* __restrict__ biou) {
    extern __shared__ char smc[];
    const unsigned smb = smem_u32(smc);
    const int tid = threadIdx.x, wid = tid >> 5, lane = tid & 31;
    const int wrow = wid & 7, ch = wid >> 3;
    const int jb = blockIdx.x * 128;           // output col block
    const unsigned AB = smb + K3_AB;

    // B fill: B[n][k] = G[k][jb+n], bf16 hi/lo, row stride 768B, XOR swizzle
    for (int idx = tid; idx < 128*384; idx += 512) {
        int k = idx % 384, n = idx / 384;
        float v = g_G[k*384 + jb + n];
        __nv_bfloat16 bh = __float2bfloat16_rn(v);
        __nv_bfloat16 bl = __float2bfloat16_rn(v - __bfloat162float(bh));
        unsigned off = (unsigned)(n*768 + ((2*k) ^ ((n & 7) << 4)));
        *(__nv_bfloat16*)(smc + off)          = bh;
        *(__nv_bfloat16*)(smc + K3_BL + off)  = bl;
    }
    __syncthreads();

    const int crow = tid >> 2, cseg = tid & 3;
    const unsigned csw = ((unsigned)((crow >> 1) & 3)) << 4;
    const unsigned cdo = (unsigned)(crow*64) + (((unsigned)cseg*16) ^ csw);

    for (int rt = blockIdx.y; rt < 391; rt += gridDim.y) {
        const size_t rbase = (size_t)rt * 128;

        // prologue: async-fill chunk 0 into buf0
        {
            const size_t go = (rbase + crow)*384 + cseg*8;
            CP_ASYNC16(AB + cdo,        (const void*)(g_Zh + go));
            CP_ASYNC16(AB + 8192 + cdo, (const void*)(g_Zl + go));
            CP_COMMIT();
        }

        float acc[4][2][4];
#pragma unroll
        for (int g = 0; g < 4; g++)
#pragma unroll
            for (int s = 0; s < 2; s++)
#pragma unroll
                for (int q = 0; q < 4; q++) acc[g][s][q] = 0.f;

        for (int c = 0; c < 12; c++) {
            if (c < 11) {   // async-fill chunk c+1 into the other buffer
                const size_t go = (rbase + crow)*384 + (c+1)*32 + cseg*8;
                unsigned dst = AB + (unsigned)(((c+1) & 1)*16384) + cdo;
                CP_ASYNC16(dst,        (const void*)(g_Zh + go));
                CP_ASYNC16(dst + 8192, (const void*)(g_Zl + go));
                CP_COMMIT();
                CP_WAIT1();
            } else {
                CP_WAIT0();
            }
            __syncthreads();
            {
                const int arow = wrow*16 + (lane & 7) + ((lane >> 3) & 1) * 8;
                const unsigned arsw = ((unsigned)((arow >> 1) & 3)) << 4;
                const int bn_l = (lane & 7) + (lane >> 4) * 8;
                const int bkb_l = ((lane >> 3) & 1) * 16;
                const unsigned abase = AB + (unsigned)((c & 1)*16384);
#pragma unroll
                for (int kk = 0; kk < 2; kk++) {
                    unsigned akb = (unsigned)(kk*32 + (lane >> 4) * 16);
                    unsigned aoff = (unsigned)(arow*64) + (akb ^ arsw);
                    unsigned ah[4], al[4];
                    ldsm4(ah, abase + aoff);
                    ldsm4(al, abase + 8192 + aoff);
                    const int bkb = c*64 + kk*32 + bkb_l;
#pragma unroll
                    for (int g = 0; g < 4; g++) {
                        int bn = ch*64 + g*16 + bn_l;
                        unsigned boff = (unsigned)(bn*768) +
                                        ((unsigned)bkb ^ ((unsigned)(bn & 7) << 4));
                        unsigned bh[4], bl[4];
                        ldsm4(bh, smb + boff);
                        ldsm4(bl, smb + K3_BL + boff);
#pragma unroll
                        for (int s = 0; s < 2; s++) {
                            mma16816(acc[g][s], ah, bh[s*2], bh[s*2+1]);
                            mma16816(acc[g][s], ah, bl[s*2], bl[s*2+1]);
                            mma16816(acc[g][s], al, bh[s*2], bh[s*2+1]);
                        }
                    }
                }
            }
            __syncthreads();   // all warps done reading buf (c&1) before it's refilled
        }

        // epilogue: IOU = acc + biou
        {
            const size_t rlo = rbase + wrow*16 + (lane >> 2);
            const size_t rhi = rlo + 8;
#pragma unroll
            for (int g = 0; g < 4; g++)
#pragma unroll
                for (int s = 0; s < 2; s++) {
                    int c = ch*64 + g*16 + s*8 + (lane & 3)*2;
                    float2 bi = *(const float2*)(biou + jb + c);
                    *(float2*)(g_IOU + rlo*384 + jb + c) =
                        make_float2(acc[g][s][0] + bi.x, acc[g][s][1] + bi.y);
                    *(float2*)(g_IOU + rhi*384 + jb + c) =
                        make_float2(acc[g][s][2] + bi.x, acc[g][s][3] + bi.y);
                }
        }
    }
}

// ---------------- K3b: gates -> out ----------------
__global__ void k3b(float* __restrict__ out) {
    int idx = blockIdx.x * blockDim.x + threadIdx.x;
    if (idx >= NN*32) return;
    int n = idx >> 5;
    int j = (idx & 31) * 4;
    const float* r = g_IOU + (size_t)n * 384;
    float4 iv = *(const float4*)(r + j);
    float4 ov = *(const float4*)(r + 128 + j);
    float4 uv = *(const float4*)(r + 256 + j);
    float4 cr = *(const float4*)(g_cred + (size_t)n*128 + j);
    float4 hc, cc;
    {
        float ig, og, ug, c, h;
        ig = 1.f/(1.f+expf(-iv.x)); og = 1.f/(1.f+expf(-ov.x)); ug = tanhf(uv.x);
        c = ig*ug + cr.x; h = og*tanhf(c); hc.x = h; cc.x = c;
        ig = 1.f/(1.f+expf(-iv.y)); og = 1.f/(1.f+expf(-ov.y)); ug = tanhf(uv.y);
        c = ig*ug + cr.y; h = og*tanhf(c); hc.y = h; cc.y = c;
        ig = 1.f/(1.f+expf(-iv.z)); og = 1.f/(1.f+expf(-ov.z)); ug = tanhf(uv.z);
        c = ig*ug + cr.z; h = og*tanhf(c); hc.z = h; cc.z = c;
        ig = 1.f/(1.f+expf(-iv.w)); og = 1.f/(1.f+expf(-ov.w)); ug = tanhf(uv.w);
        c = ig*ug + cr.w; h = og*tanhf(c); hc.w = h; cc.w = c;
    }
    *(float4*)(out + (size_t)n*128 + j) = hc;
    *(float4*)(out + (size_t)NN*128 + (size_t)n*128 + j) = cc;
}

// ---------------- launcher ----------------
extern "C" void kernel_launch(void* const* d_in, const int* in_sizes, int n_in,
                              void* d_out, int out_size) {
    const float* x      = (const float*)d_in[0];
    const float* h_mail = (const float*)d_in[1];
    const float* c_mail = (const float*)d_in[2];
    const float* Wiou   = (const float*)d_in[3];
    const float* Uiou   = (const float*)d_in[4];
    const float* biou   = (const float*)d_in[5];
    const float* Of     = (const float*)d_in[6];
    const float* Zf     = (const float*)d_in[7];
    const float* Qf     = (const float*)d_in[8];
    const float* Kf     = (const float*)d_in[9];
    const float* vf     = (const float*)d_in[10];
    const float* Wa     = (const float*)d_in[11];
    const float* Wd     = (const float*)d_in[12];
    const float* Vf     = (const float*)d_in[13];
    const int*   etype  = (const int*)d_in[14];
    float* out = (float*)d_out;

    cudaFuncSetAttribute(k2,  cudaFuncAttributeMaxDynamicSharedMemorySize, K2_SMEM);
    cudaFuncSetAttribute(k3a, cudaFuncAttributeMaxDynamicSharedMemorySize, K3_SMEM);

    k1a<<<128, 256>>>(Wa, Wd, vf);
    k1b<<<577, 256>>>(Uiou, Wiou, Qf, Vf);
    k1c<<<6250, 256>>>(x);
    k2<<<148, 512, K2_SMEM>>>(h_mail, c_mail, Kf, Vf, Of, Zf, etype);
    k3a<<<dim3(3, 49), 512, K3_SMEM>>>(biou);
    k3b<<<6250, 256>>>(out);
}